// round 9
// baseline (speedup 1.0000x reference)
#include <cuda_runtime.h>
#include <cuda_bf16.h>
#include <mma.h>
#include <cstdint>

using namespace nvcuda;

// ---------------------------------------------------------------------------
// GraphSAGE 3-layer, aggregate-then-transform:
//   h' = relu( (gather(h)/deg) @ Wl + h @ Wr + b )
// Per layer: yr-GEMM (tensor pipe, main stream) runs CONCURRENTLY with
// gather (L2 pipe, aux stream, 0 smem -> co-resident on same SMs), then the
// Wl-GEMM consumes agg with mean in its prologue and yr+b+relu in epilogue.
// GEMMs: bf16 Markidis split (xh*wh + xh*wl + xl*wh), 256-row tiles.
// ---------------------------------------------------------------------------

#define N_NODES 100000
#define N_EDGES 1600000
#define LDXS 136

__device__ float g_yr[(size_t)N_NODES * 128];
__device__ float g_h0[(size_t)N_NODES * 128];
__device__ float g_h1[(size_t)N_NODES * 128];
__device__ float g_agg[(size_t)N_NODES * 128];
__device__ int   g_cnt[N_NODES];
__device__ int   g_off[N_NODES];
__device__ int   g_cur[N_NODES];
__device__ int   g_csr[N_EDGES];
__device__ int   g_bsum[128];
__device__ int   g_is64;
__device__ __nv_bfloat16 g_whi[6 * 16384];
__device__ __nv_bfloat16 g_wlo[6 * 16384];

// --------------------------- edge dtype probe ------------------------------
__global__ void detect_kernel(const void* ei) {
    const long long* e64 = (const long long*)ei;
    int is64 = 1;
    for (int i = 0; i < 64; i++) {
        long long v = e64[i];
        if (v < 0 || v >= N_NODES) { is64 = 0; break; }
    }
    g_is64 = is64;
}

__device__ __forceinline__ int load_idx(const void* ei, long long pos) {
    if (g_is64) return (int)((const long long*)ei)[pos];
    return ((const int*)ei)[pos];
}

// ------------------------------- CSR build ---------------------------------
__global__ void zero_int_kernel(int* __restrict__ p, int n) {
    int i = blockIdx.x * blockDim.x + threadIdx.x;
    if (i < n) p[i] = 0;
}

__global__ void hist_kernel(const void* __restrict__ ei, int* __restrict__ cnt) {
    int e = blockIdx.x * blockDim.x + threadIdx.x;
    if (e < N_EDGES) {
        int d = load_idx(ei, (long long)N_EDGES + e);
        if ((unsigned)d < N_NODES) atomicAdd(&cnt[d], 1);
    }
}

__global__ void blockreduce_kernel(const int* __restrict__ cnt, int* __restrict__ bsum) {
    __shared__ int sm[256];
    int b = blockIdx.x, t = threadIdx.x;
    int base = b * 1024 + t * 4;
    int s = 0;
    #pragma unroll
    for (int i = 0; i < 4; i++) {
        int idx = base + i;
        if (idx < N_NODES) s += cnt[idx];
    }
    sm[t] = s; __syncthreads();
    for (int st = 128; st > 0; st >>= 1) {
        if (t < st) sm[t] += sm[t + st];
        __syncthreads();
    }
    if (t == 0) bsum[b] = sm[0];
}

__global__ void scanpart_kernel(int* __restrict__ bsum, int nb) {
    if (threadIdx.x == 0) {
        int acc = 0;
        for (int i = 0; i < nb; i++) { int v = bsum[i]; bsum[i] = acc; acc += v; }
    }
}

__global__ void scanfinal_kernel(const int* __restrict__ cnt, const int* __restrict__ bsum,
                                 int* __restrict__ off, int* __restrict__ cur) {
    __shared__ int sm[256];
    int b = blockIdx.x, t = threadIdx.x;
    int base = b * 1024 + t * 4;
    int v[4]; int s = 0;
    #pragma unroll
    for (int i = 0; i < 4; i++) {
        int idx = base + i;
        v[i] = (idx < N_NODES) ? cnt[idx] : 0;
        s += v[i];
    }
    sm[t] = s; __syncthreads();
    for (int st = 1; st < 256; st <<= 1) {
        int x = (t >= st) ? sm[t - st] : 0;
        __syncthreads();
        sm[t] += x;
        __syncthreads();
    }
    int run = sm[t] - s + bsum[b];
    #pragma unroll
    for (int i = 0; i < 4; i++) {
        int idx = base + i;
        if (idx < N_NODES) { off[idx] = run; cur[idx] = run; }
        run += v[i];
    }
}

__global__ void fill_kernel(const void* __restrict__ ei, int* __restrict__ cur,
                            int* __restrict__ csr) {
    int e = blockIdx.x * blockDim.x + threadIdx.x;
    if (e < N_EDGES) {
        int s = load_idx(ei, e);
        int d = load_idx(ei, (long long)N_EDGES + e);
        if ((unsigned)s < N_NODES && (unsigned)d < N_NODES) {
            int p = atomicAdd(&cur[d], 1);
            csr[p] = s;
        }
    }
}

// --------------------- weight split (fp32 -> bf16 hi/lo) -------------------
__global__ void wsplit_kernel(const float* __restrict__ W,
                              __nv_bfloat16* __restrict__ hi,
                              __nv_bfloat16* __restrict__ lo, int n) {
    int i = blockIdx.x * blockDim.x + threadIdx.x;
    if (i < n) {
        float w = W[i];
        __nv_bfloat16 h = __float2bfloat16(w);
        hi[i] = h;
        lo[i] = __float2bfloat16(w - __bfloat162float(h));
    }
}

__device__ __forceinline__ void split2(float a, float b, __nv_bfloat162& h2, __nv_bfloat162& l2) {
    __nv_bfloat16 ha = __float2bfloat16(a), hb = __float2bfloat16(b);
    h2 = __nv_bfloat162(ha, hb);
    l2 = __nv_bfloat162(__float2bfloat16(a - __bfloat162float(ha)),
                        __float2bfloat16(b - __bfloat162float(hb)));
}

// ---------------------------------------------------------------------------
// Tensor-core GEMM: Y = f( src' @ W ), src' = src (MEAN=false) or src/deg.
//  EPI 0: Y = src'@W              (yr pass)
//  EPI 1: Y = relu(src'@W + yr + b)
//  EPI 2: Y = src'@W + yr + b
// Block: 256 rows, 256 threads (8 warps), W hi/lo staged in smem.
// ---------------------------------------------------------------------------
template <int DOUT, bool MEAN, int EPI>
__global__ __launch_bounds__(256) void gemm_tc(
    const float* __restrict__ src, const int* __restrict__ cnt,
    const __nv_bfloat16* __restrict__ Whi, const __nv_bfloat16* __restrict__ Wlo,
    const float* __restrict__ yr, const float* __restrict__ bias,
    float* __restrict__ Y)
{
    constexpr int LDW = DOUT + 8;
    constexpr int ROWS = 256;
    extern __shared__ __nv_bfloat16 smem[];
    __nv_bfloat16* sXhi = smem;                      // [256][LDXS]
    __nv_bfloat16* sXlo = sXhi + ROWS * LDXS;        // [256][LDXS]
    __nv_bfloat16* sWh  = sXlo + ROWS * LDXS;        // [128][LDW]
    __nv_bfloat16* sWl  = sWh + 128 * LDW;

    const int row0 = blockIdx.x * ROWS;
    const int t = threadIdx.x;

    // ---- stage W hi/lo ----
    {
        constexpr int C8 = DOUT / 8;
        const uint4* gh = reinterpret_cast<const uint4*>(Whi);
        const uint4* gl = reinterpret_cast<const uint4*>(Wlo);
        for (int i = t; i < 128 * C8; i += 256) {
            int r = i / C8, c8 = i % C8;
            int so = r * LDW + c8 * 8;
            *reinterpret_cast<uint4*>(&sWh[so]) = gh[i];
            *reinterpret_cast<uint4*>(&sWl[so]) = gl[i];
        }
    }

    // ---- prologue: load src (optionally /deg), split to bf16 hi/lo ----
    for (int i = t; i < ROWS * 32; i += 256) {
        int r = i >> 5, c4 = i & 31;
        int gr = row0 + r;
        float4 v = make_float4(0.f, 0.f, 0.f, 0.f);
        if (gr < N_NODES) {
            v = reinterpret_cast<const float4*>(src)[(size_t)gr * 32 + c4];
            if (MEAN) {
                float dinv = 1.0f / fmaxf((float)cnt[gr], 1.0f);
                v.x *= dinv; v.y *= dinv; v.z *= dinv; v.w *= dinv;
            }
        }
        __nv_bfloat162 h0, l0, h1, l1;
        split2(v.x, v.y, h0, l0);
        split2(v.z, v.w, h1, l1);
        int base = r * LDXS + c4 * 4;
        *reinterpret_cast<__nv_bfloat162*>(&sXhi[base])     = h0;
        *reinterpret_cast<__nv_bfloat162*>(&sXhi[base + 2]) = h1;
        *reinterpret_cast<__nv_bfloat162*>(&sXlo[base])     = l0;
        *reinterpret_cast<__nv_bfloat162*>(&sXlo[base + 2]) = l1;
    }
    __syncthreads();

    // ---- warp tiling ----
    constexpr int WN = (DOUT == 128) ? 2 : 1;
    constexpr int WM = 8 / WN;              // 4 or 8
    constexpr int RW = ROWS / WM;           // 64 or 32
    constexpr int MFRAG = RW / 16;          // 4 or 2
    const int warp = t >> 5;
    const int wm = warp % WM;
    const int wn = warp / WM;
    const int mbase = wm * RW;
    const int nbase = wn * 64;

    wmma::fragment<wmma::accumulator, 16, 16, 16, float> acc[MFRAG][4];
    #pragma unroll
    for (int mf = 0; mf < MFRAG; mf++)
        #pragma unroll
        for (int nf = 0; nf < 4; nf++)
            wmma::fill_fragment(acc[mf][nf], 0.0f);

    #pragma unroll
    for (int k = 0; k < 128; k += 16) {
        wmma::fragment<wmma::matrix_a, 16, 16, 16, __nv_bfloat16, wmma::row_major> ahi[MFRAG], alo[MFRAG];
        #pragma unroll
        for (int mf = 0; mf < MFRAG; mf++) {
            wmma::load_matrix_sync(ahi[mf], &sXhi[(mbase + mf * 16) * LDXS + k], LDXS);
            wmma::load_matrix_sync(alo[mf], &sXlo[(mbase + mf * 16) * LDXS + k], LDXS);
        }
        #pragma unroll
        for (int nf = 0; nf < 4; nf++) {
            int n0 = nbase + nf * 16;
            wmma::fragment<wmma::matrix_b, 16, 16, 16, __nv_bfloat16, wmma::row_major> bh, bl;
            wmma::load_matrix_sync(bh, &sWh[k * LDW + n0], LDW);
            wmma::load_matrix_sync(bl, &sWl[k * LDW + n0], LDW);
            #pragma unroll
            for (int mf = 0; mf < MFRAG; mf++) {
                wmma::mma_sync(acc[mf][nf], ahi[mf], bh, acc[mf][nf]);
                wmma::mma_sync(acc[mf][nf], ahi[mf], bl, acc[mf][nf]);
                wmma::mma_sync(acc[mf][nf], alo[mf], bh, acc[mf][nf]);
            }
        }
    }

    if (EPI == 0) {
        // direct store (N_NODES % 16 == 0 -> fragment-granular guard)
        #pragma unroll
        for (int mf = 0; mf < MFRAG; mf++) {
            int grow = row0 + mbase + mf * 16;
            if (grow < N_NODES) {
                #pragma unroll
                for (int nf = 0; nf < 4; nf++)
                    wmma::store_matrix_sync(Y + (size_t)grow * DOUT + nbase + nf * 16,
                                            acc[mf][nf], DOUT, wmma::mem_row_major);
            }
        }
    } else {
        // stage accumulators in (reused X) smem, then fused epilogue
        constexpr int LDE = DOUT + 4;
        float* sEp = reinterpret_cast<float*>(smem);   // [256][LDE] fp32
        __syncthreads();   // everyone done reading sXhi/sXlo
        #pragma unroll
        for (int mf = 0; mf < MFRAG; mf++) {
            #pragma unroll
            for (int nf = 0; nf < 4; nf++)
                wmma::store_matrix_sync(&sEp[(mbase + mf * 16) * LDE + nbase + nf * 16],
                                        acc[mf][nf], LDE, wmma::mem_row_major);
        }
        __syncthreads();
        constexpr int C4 = DOUT / 4;
        for (int i = t; i < ROWS * C4; i += 256) {
            int r = i / C4, c4 = i % C4;
            int gr = row0 + r;
            if (gr < N_NODES) {
                float4 a = *reinterpret_cast<const float4*>(&sEp[r * LDE + c4 * 4]);
                float4 yv = reinterpret_cast<const float4*>(yr)[(size_t)gr * C4 + c4];
                float4 bb = reinterpret_cast<const float4*>(bias)[c4];
                float4 o;
                o.x = a.x + yv.x + bb.x;
                o.y = a.y + yv.y + bb.y;
                o.z = a.z + yv.z + bb.z;
                o.w = a.w + yv.w + bb.w;
                if (EPI == 1) {
                    o.x = fmaxf(o.x, 0.f); o.y = fmaxf(o.y, 0.f);
                    o.z = fmaxf(o.z, 0.f); o.w = fmaxf(o.w, 0.f);
                }
                reinterpret_cast<float4*>(Y)[(size_t)gr * C4 + c4] = o;
            }
        }
    }
}

// ---------------------------------------------------------------------------
// Gather: agg[n] = sum_{s in N(n)} h[s]  (128 ch, one warp per node, 0 smem)
// ---------------------------------------------------------------------------
__global__ __launch_bounds__(256) void gather128_agg_kernel(
    const float* __restrict__ h,
    const int* __restrict__ csr, const int* __restrict__ off,
    const int* __restrict__ cnt, float* __restrict__ agg)
{
    int warp = (blockIdx.x * 256 + threadIdx.x) >> 5;
    int lane = threadIdx.x & 31;
    if (warp >= N_NODES) return;

    const int c = cnt[warp];
    const int o = off[warp];
    const float4* __restrict__ h4 = reinterpret_cast<const float4*>(h);

    float4 acc = make_float4(0.f, 0.f, 0.f, 0.f);
    int j = 0;
    for (; j + 4 <= c; j += 4) {
        int s0 = csr[o + j + 0];
        int s1 = csr[o + j + 1];
        int s2 = csr[o + j + 2];
        int s3 = csr[o + j + 3];
        float4 a0 = h4[(size_t)s0 * 32 + lane];
        float4 a1 = h4[(size_t)s1 * 32 + lane];
        float4 a2 = h4[(size_t)s2 * 32 + lane];
        float4 a3 = h4[(size_t)s3 * 32 + lane];
        acc.x += a0.x + a1.x + a2.x + a3.x;
        acc.y += a0.y + a1.y + a2.y + a3.y;
        acc.z += a0.z + a1.z + a2.z + a3.z;
        acc.w += a0.w + a1.w + a2.w + a3.w;
    }
    for (; j < c; j++) {
        int s = csr[o + j];
        float4 a = h4[(size_t)s * 32 + lane];
        acc.x += a.x; acc.y += a.y; acc.z += a.z; acc.w += a.w;
    }
    reinterpret_cast<float4*>(agg)[(size_t)warp * 32 + lane] = acc;
}

// ---------------------------------------------------------------------------
extern "C" void kernel_launch(void* const* d_in, const int* in_sizes, int n_in,
                              void* d_out, int out_size)
{
    const float* x   = (const float*)d_in[0];
    const void*  ei  = d_in[1];
    const float* Wl0 = (const float*)d_in[2];
    const float* Wr0 = (const float*)d_in[3];
    const float* b0  = (const float*)d_in[4];
    const float* Wl1 = (const float*)d_in[5];
    const float* Wr1 = (const float*)d_in[6];
    const float* b1  = (const float*)d_in[7];
    const float* Wl2 = (const float*)d_in[8];
    const float* Wr2 = (const float*)d_in[9];
    const float* b2  = (const float*)d_in[10];
    float* out = (float*)d_out;

    const int SMEM_X   = 256 * LDXS * 2 * (int)sizeof(__nv_bfloat16);               // 139264
    const int SMEM_128 = SMEM_X + 2 * 128 * (128 + 8) * (int)sizeof(__nv_bfloat16); // 208896
    const int SMEM_64  = SMEM_X + 2 * 128 * (64 + 8)  * (int)sizeof(__nv_bfloat16); // 176128

    static float *p_yr = nullptr, *p_h0 = nullptr, *p_h1 = nullptr, *p_agg = nullptr;
    static int *p_cnt = nullptr, *p_off = nullptr, *p_cur = nullptr, *p_csr = nullptr, *p_bsum = nullptr;
    static __nv_bfloat16 *p_whi = nullptr, *p_wlo = nullptr;
    static cudaStream_t s_aux = nullptr;
    static cudaEvent_t ev[8];
    if (!p_yr) {
        cudaGetSymbolAddress((void**)&p_yr,   g_yr);
        cudaGetSymbolAddress((void**)&p_h0,   g_h0);
        cudaGetSymbolAddress((void**)&p_h1,   g_h1);
        cudaGetSymbolAddress((void**)&p_agg,  g_agg);
        cudaGetSymbolAddress((void**)&p_cnt,  g_cnt);
        cudaGetSymbolAddress((void**)&p_off,  g_off);
        cudaGetSymbolAddress((void**)&p_cur,  g_cur);
        cudaGetSymbolAddress((void**)&p_csr,  g_csr);
        cudaGetSymbolAddress((void**)&p_bsum, g_bsum);
        cudaGetSymbolAddress((void**)&p_whi,  g_whi);
        cudaGetSymbolAddress((void**)&p_wlo,  g_wlo);
        cudaStreamCreateWithFlags(&s_aux, cudaStreamNonBlocking);
        for (int i = 0; i < 8; i++)
            cudaEventCreateWithFlags(&ev[i], cudaEventDisableTiming);
        cudaFuncSetAttribute(gemm_tc<128, false, 0>, cudaFuncAttributeMaxDynamicSharedMemorySize, SMEM_128);
        cudaFuncSetAttribute(gemm_tc<128, true,  1>, cudaFuncAttributeMaxDynamicSharedMemorySize, SMEM_128);
        cudaFuncSetAttribute(gemm_tc<64,  false, 0>, cudaFuncAttributeMaxDynamicSharedMemorySize, SMEM_64);
        cudaFuncSetAttribute(gemm_tc<64,  true,  2>, cudaFuncAttributeMaxDynamicSharedMemorySize, SMEM_64);
    }

    const int NB_GEMM = (N_NODES + 255) / 256;    // 391
    const int NB_SCAN = (N_NODES + 1023) / 1024;
    const int NB_EDGE = (N_EDGES + 255) / 256;
    const int NB_G128 = (N_NODES * 32 + 255) / 256;

    // ---- aux stream: CSR build, then layer-0 gather on x (input is ready) ----
    cudaEventRecord(ev[0], 0);
    cudaStreamWaitEvent(s_aux, ev[0], 0);
    detect_kernel<<<1, 1, 0, s_aux>>>(ei);
    zero_int_kernel<<<(N_NODES + 255) / 256, 256, 0, s_aux>>>(p_cnt, N_NODES);
    hist_kernel<<<NB_EDGE, 256, 0, s_aux>>>(ei, p_cnt);
    blockreduce_kernel<<<NB_SCAN, 256, 0, s_aux>>>(p_cnt, p_bsum);
    scanpart_kernel<<<1, 32, 0, s_aux>>>(p_bsum, NB_SCAN);
    scanfinal_kernel<<<NB_SCAN, 256, 0, s_aux>>>(p_cnt, p_bsum, p_off, p_cur);
    fill_kernel<<<NB_EDGE, 256, 0, s_aux>>>(ei, p_cur, p_csr);
    gather128_agg_kernel<<<NB_G128, 256, 0, s_aux>>>(x, p_csr, p_off, p_cnt, p_agg);
    cudaEventRecord(ev[1], s_aux);

    // ---- main: weight splits + yr0 (overlap CSR+gather0) ----
    wsplit_kernel<<<64, 256>>>(Wl0, p_whi + 0 * 16384, p_wlo + 0 * 16384, 16384);
    wsplit_kernel<<<64, 256>>>(Wr0, p_whi + 1 * 16384, p_wlo + 1 * 16384, 16384);
    wsplit_kernel<<<64, 256>>>(Wl1, p_whi + 2 * 16384, p_wlo + 2 * 16384, 16384);
    wsplit_kernel<<<64, 256>>>(Wr1, p_whi + 3 * 16384, p_wlo + 3 * 16384, 16384);
    wsplit_kernel<<<32, 256>>>(Wl2, p_whi + 4 * 16384, p_wlo + 4 * 16384, 8192);
    wsplit_kernel<<<32, 256>>>(Wr2, p_whi + 5 * 16384, p_wlo + 5 * 16384, 8192);

    // yr0 = x @ Wr0
    gemm_tc<128, false, 0><<<NB_GEMM, 256, SMEM_128>>>(
        x, nullptr, p_whi + 1 * 16384, p_wlo + 1 * 16384, nullptr, nullptr, p_yr);
    // h0 = relu(mean(agg_x) @ Wl0 + yr0 + b0)
    cudaStreamWaitEvent(0, ev[1], 0);
    gemm_tc<128, true, 1><<<NB_GEMM, 256, SMEM_128>>>(
        p_agg, p_cnt, p_whi + 0 * 16384, p_wlo + 0 * 16384, p_yr, b0, p_h0);

    // ---- Layer 1: gather(h0) on aux  ||  yr1 = h0 @ Wr1 on main ----
    cudaEventRecord(ev[2], 0);
    cudaStreamWaitEvent(s_aux, ev[2], 0);
    gather128_agg_kernel<<<NB_G128, 256, 0, s_aux>>>(p_h0, p_csr, p_off, p_cnt, p_agg);
    cudaEventRecord(ev[3], s_aux);
    gemm_tc<128, false, 0><<<NB_GEMM, 256, SMEM_128>>>(
        p_h0, nullptr, p_whi + 3 * 16384, p_wlo + 3 * 16384, nullptr, nullptr, p_yr);
    cudaStreamWaitEvent(0, ev[3], 0);
    gemm_tc<128, true, 1><<<NB_GEMM, 256, SMEM_128>>>(
        p_agg, p_cnt, p_whi + 2 * 16384, p_wlo + 2 * 16384, p_yr, b1, p_h1);

    // ---- Layer 2: gather(h1) on aux  ||  yr2 = h1 @ Wr2 on main ----
    cudaEventRecord(ev[4], 0);
    cudaStreamWaitEvent(s_aux, ev[4], 0);
    gather128_agg_kernel<<<NB_G128, 256, 0, s_aux>>>(p_h1, p_csr, p_off, p_cnt, p_agg);
    cudaEventRecord(ev[5], s_aux);
    gemm_tc<64, false, 0><<<NB_GEMM, 256, SMEM_64>>>(
        p_h1, nullptr, p_whi + 5 * 16384, p_wlo + 5 * 16384, nullptr, nullptr, p_yr);
    cudaStreamWaitEvent(0, ev[5], 0);
    gemm_tc<64, true, 2><<<NB_GEMM, 256, SMEM_64>>>(
        p_agg, p_cnt, p_whi + 4 * 16384, p_wlo + 4 * 16384, p_yr, b2, out);
}

// round 10
// speedup vs baseline: 1.3069x; 1.3069x over previous
#include <cuda_runtime.h>
#include <cuda_bf16.h>
#include <cuda_fp16.h>
#include <mma.h>
#include <cstdint>

using namespace nvcuda;

// ---------------------------------------------------------------------------
// GraphSAGE 3-layer. Transform-then-aggregate + CSR gather (R8 structure).
// GEMMs: bf16 Markidis split on tensor cores (xh*wh + xh*wl + xl*wh).
// NEW vs R8: yl stored fp16 (feeds only the gather -> half the gather
// traffic); final combine fused into the 64-ch gather.
// ---------------------------------------------------------------------------

#define N_NODES 100000
#define N_EDGES 1600000
#define LDXS 136   // X smem leading dim (bf16 elems)

__device__ __half g_ylh[(size_t)N_NODES * 128];
__device__ float  g_yr[(size_t)N_NODES * 128];
__device__ float  g_bufA[(size_t)N_NODES * 128];   // agg
__device__ float  g_bufB[(size_t)N_NODES * 128];   // agg
__device__ int    g_cnt[N_NODES];
__device__ int    g_off[N_NODES];
__device__ int    g_cur[N_NODES];
__device__ int    g_csr[N_EDGES];
__device__ int    g_bsum[128];
__device__ int    g_is64;
__device__ __nv_bfloat16 g_whi[6 * 16384];
__device__ __nv_bfloat16 g_wlo[6 * 16384];

// --------------------------- edge dtype probe ------------------------------
__global__ void detect_kernel(const void* ei) {
    const long long* e64 = (const long long*)ei;
    int is64 = 1;
    for (int i = 0; i < 64; i++) {
        long long v = e64[i];
        if (v < 0 || v >= N_NODES) { is64 = 0; break; }
    }
    g_is64 = is64;
}

__device__ __forceinline__ int load_idx(const void* ei, long long pos) {
    if (g_is64) return (int)((const long long*)ei)[pos];
    return ((const int*)ei)[pos];
}

// ------------------------------- CSR build ---------------------------------
__global__ void zero_int_kernel(int* __restrict__ p, int n) {
    int i = blockIdx.x * blockDim.x + threadIdx.x;
    if (i < n) p[i] = 0;
}

__global__ void hist_kernel(const void* __restrict__ ei, int* __restrict__ cnt) {
    int e = blockIdx.x * blockDim.x + threadIdx.x;
    if (e < N_EDGES) {
        int d = load_idx(ei, (long long)N_EDGES + e);
        if ((unsigned)d < N_NODES) atomicAdd(&cnt[d], 1);
    }
}

__global__ void blockreduce_kernel(const int* __restrict__ cnt, int* __restrict__ bsum) {
    __shared__ int sm[256];
    int b = blockIdx.x, t = threadIdx.x;
    int base = b * 1024 + t * 4;
    int s = 0;
    #pragma unroll
    for (int i = 0; i < 4; i++) {
        int idx = base + i;
        if (idx < N_NODES) s += cnt[idx];
    }
    sm[t] = s; __syncthreads();
    for (int st = 128; st > 0; st >>= 1) {
        if (t < st) sm[t] += sm[t + st];
        __syncthreads();
    }
    if (t == 0) bsum[b] = sm[0];
}

__global__ void scanpart_kernel(int* __restrict__ bsum, int nb) {
    if (threadIdx.x == 0) {
        int acc = 0;
        for (int i = 0; i < nb; i++) { int v = bsum[i]; bsum[i] = acc; acc += v; }
    }
}

__global__ void scanfinal_kernel(const int* __restrict__ cnt, const int* __restrict__ bsum,
                                 int* __restrict__ off, int* __restrict__ cur) {
    __shared__ int sm[256];
    int b = blockIdx.x, t = threadIdx.x;
    int base = b * 1024 + t * 4;
    int v[4]; int s = 0;
    #pragma unroll
    for (int i = 0; i < 4; i++) {
        int idx = base + i;
        v[i] = (idx < N_NODES) ? cnt[idx] : 0;
        s += v[i];
    }
    sm[t] = s; __syncthreads();
    for (int st = 1; st < 256; st <<= 1) {
        int x = (t >= st) ? sm[t - st] : 0;
        __syncthreads();
        sm[t] += x;
        __syncthreads();
    }
    int run = sm[t] - s + bsum[b];
    #pragma unroll
    for (int i = 0; i < 4; i++) {
        int idx = base + i;
        if (idx < N_NODES) { off[idx] = run; cur[idx] = run; }
        run += v[i];
    }
}

__global__ void fill_kernel(const void* __restrict__ ei, int* __restrict__ cur,
                            int* __restrict__ csr) {
    int e = blockIdx.x * blockDim.x + threadIdx.x;
    if (e < N_EDGES) {
        int s = load_idx(ei, e);
        int d = load_idx(ei, (long long)N_EDGES + e);
        if ((unsigned)s < N_NODES && (unsigned)d < N_NODES) {
            int p = atomicAdd(&cur[d], 1);
            csr[p] = s;
        }
    }
}

// --------------------- weight split (fp32 -> bf16 hi/lo) -------------------
__global__ void wsplit_kernel(const float* __restrict__ W,
                              __nv_bfloat16* __restrict__ hi,
                              __nv_bfloat16* __restrict__ lo, int n) {
    int i = blockIdx.x * blockDim.x + threadIdx.x;
    if (i < n) {
        float w = W[i];
        __nv_bfloat16 h = __float2bfloat16(w);
        hi[i] = h;
        lo[i] = __float2bfloat16(w - __bfloat162float(h));
    }
}

__device__ __forceinline__ void split2(float a, float b, __nv_bfloat162& h2, __nv_bfloat162& l2) {
    __nv_bfloat16 ha = __float2bfloat16(a), hb = __float2bfloat16(b);
    h2 = __nv_bfloat162(ha, hb);
    l2 = __nv_bfloat162(__float2bfloat16(a - __bfloat162float(ha)),
                        __float2bfloat16(b - __bfloat162float(hb)));
}

// ---------------------------------------------------------------------------
// Dual tensor-core GEMM: Yl(half) = H@Wl, Yr(fp32) = H@Wr
// H is X (PRO=false) or relu(agg/max(deg,1) + yrIn + bias) (PRO=true).
// X split to bf16 hi/lo in smem; all 4 weight matrices staged in smem.
// Yl converted to fp16 via smem restage (reuses X region after mma).
// Block: 128 rows, 256 threads (8 warps).
// ---------------------------------------------------------------------------
template <int DOUT, bool PRO>
__global__ __launch_bounds__(256) void gemm_dual_bf16(
    const float* __restrict__ X,
    const float* __restrict__ agg, const float* __restrict__ yrIn,
    const int* __restrict__ cnt, const float* __restrict__ bias,
    const __nv_bfloat16* __restrict__ Wlhi, const __nv_bfloat16* __restrict__ Wllo,
    const __nv_bfloat16* __restrict__ Wrhi, const __nv_bfloat16* __restrict__ Wrlo,
    __half* __restrict__ Yl, float* __restrict__ Yr)
{
    constexpr int LDW = DOUT + 8;              // W smem leading dim
    extern __shared__ __nv_bfloat16 smem[];
    __nv_bfloat16* sXhi = smem;                       // [128][LDXS]
    __nv_bfloat16* sXlo = sXhi + 128 * LDXS;          // [128][LDXS]
    __nv_bfloat16* sWlh = sXlo + 128 * LDXS;          // [128][LDW]
    __nv_bfloat16* sWll = sWlh + 128 * LDW;
    __nv_bfloat16* sWrh = sWll + 128 * LDW;
    __nv_bfloat16* sWrl = sWrh + 128 * LDW;

    const int row0 = blockIdx.x * 128;
    const int t = threadIdx.x;

    // ---- stage W (vectorized) ----
    {
        constexpr int C8 = DOUT / 8;
        const uint4* gl_h = reinterpret_cast<const uint4*>(Wlhi);
        const uint4* gl_l = reinterpret_cast<const uint4*>(Wllo);
        const uint4* gr_h = reinterpret_cast<const uint4*>(Wrhi);
        const uint4* gr_l = reinterpret_cast<const uint4*>(Wrlo);
        for (int i = t; i < 128 * C8; i += 256) {
            int r = i / C8, c8 = i % C8;
            int so = r * LDW + c8 * 8;
            *reinterpret_cast<uint4*>(&sWlh[so]) = gl_h[i];
            *reinterpret_cast<uint4*>(&sWll[so]) = gl_l[i];
            *reinterpret_cast<uint4*>(&sWrh[so]) = gr_h[i];
            *reinterpret_cast<uint4*>(&sWrl[so]) = gr_l[i];
        }
    }

    // ---- prologue: build H tile, split to bf16 hi/lo ----
    for (int i = t; i < 128 * 32; i += 256) {
        int r = i >> 5, c4 = i & 31;
        int gr = row0 + r;
        float4 v = make_float4(0.f, 0.f, 0.f, 0.f);
        if (gr < N_NODES) {
            if (PRO) {
                float4 a  = reinterpret_cast<const float4*>(agg)[(size_t)gr * 32 + c4];
                float4 yv = reinterpret_cast<const float4*>(yrIn)[(size_t)gr * 32 + c4];
                float4 bb = reinterpret_cast<const float4*>(bias)[c4];
                float dinv = 1.0f / fmaxf((float)cnt[gr], 1.0f);
                v.x = fmaxf(a.x * dinv + yv.x + bb.x, 0.f);
                v.y = fmaxf(a.y * dinv + yv.y + bb.y, 0.f);
                v.z = fmaxf(a.z * dinv + yv.z + bb.z, 0.f);
                v.w = fmaxf(a.w * dinv + yv.w + bb.w, 0.f);
            } else {
                v = reinterpret_cast<const float4*>(X + (size_t)gr * 128)[c4];
            }
        }
        __nv_bfloat162 h0, l0, h1, l1;
        split2(v.x, v.y, h0, l0);
        split2(v.z, v.w, h1, l1);
        int base = r * LDXS + c4 * 4;
        *reinterpret_cast<__nv_bfloat162*>(&sXhi[base])     = h0;
        *reinterpret_cast<__nv_bfloat162*>(&sXhi[base + 2]) = h1;
        *reinterpret_cast<__nv_bfloat162*>(&sXlo[base])     = l0;
        *reinterpret_cast<__nv_bfloat162*>(&sXlo[base + 2]) = l1;
    }
    __syncthreads();

    // ---- warp tiling ----
    constexpr int WN = DOUT / 64;          // 2 or 1
    constexpr int WM = 8 / WN;             // 4 or 8
    constexpr int MFRAG = 128 / (WM * 16); // 2 or 1
    const int warp = t >> 5;
    const int wm = warp % WM;
    const int wn = warp / WM;
    const int mbase = wm * MFRAG * 16;
    const int nbase = wn * 64;

    wmma::fragment<wmma::accumulator, 16, 16, 16, float> accl[MFRAG][4], accr[MFRAG][4];
    #pragma unroll
    for (int mf = 0; mf < MFRAG; mf++)
        #pragma unroll
        for (int nf = 0; nf < 4; nf++) {
            wmma::fill_fragment(accl[mf][nf], 0.0f);
            wmma::fill_fragment(accr[mf][nf], 0.0f);
        }

    #pragma unroll
    for (int k = 0; k < 128; k += 16) {
        wmma::fragment<wmma::matrix_a, 16, 16, 16, __nv_bfloat16, wmma::row_major> ahi[MFRAG], alo[MFRAG];
        #pragma unroll
        for (int mf = 0; mf < MFRAG; mf++) {
            wmma::load_matrix_sync(ahi[mf], &sXhi[(mbase + mf * 16) * LDXS + k], LDXS);
            wmma::load_matrix_sync(alo[mf], &sXlo[(mbase + mf * 16) * LDXS + k], LDXS);
        }
        #pragma unroll
        for (int nf = 0; nf < 4; nf++) {
            int n0 = nbase + nf * 16;
            wmma::fragment<wmma::matrix_b, 16, 16, 16, __nv_bfloat16, wmma::row_major> bhl, bll, bhr, blr;
            wmma::load_matrix_sync(bhl, &sWlh[k * LDW + n0], LDW);
            wmma::load_matrix_sync(bll, &sWll[k * LDW + n0], LDW);
            wmma::load_matrix_sync(bhr, &sWrh[k * LDW + n0], LDW);
            wmma::load_matrix_sync(blr, &sWrl[k * LDW + n0], LDW);
            #pragma unroll
            for (int mf = 0; mf < MFRAG; mf++) {
                wmma::mma_sync(accl[mf][nf], ahi[mf], bhl, accl[mf][nf]);
                wmma::mma_sync(accl[mf][nf], ahi[mf], bll, accl[mf][nf]);
                wmma::mma_sync(accl[mf][nf], alo[mf], bhl, accl[mf][nf]);
                wmma::mma_sync(accr[mf][nf], ahi[mf], bhr, accr[mf][nf]);
                wmma::mma_sync(accr[mf][nf], ahi[mf], blr, accr[mf][nf]);
                wmma::mma_sync(accr[mf][nf], alo[mf], bhr, accr[mf][nf]);
            }
        }
    }

    // ---- Yr: direct fragment store (fp32) ----
    #pragma unroll
    for (int mf = 0; mf < MFRAG; mf++) {
        int grow = row0 + mbase + mf * 16;
        if (grow < N_NODES) {
            #pragma unroll
            for (int nf = 0; nf < 4; nf++)
                wmma::store_matrix_sync(Yr + (size_t)grow * DOUT + nbase + nf * 16,
                                        accr[mf][nf], DOUT, wmma::mem_row_major);
        }
    }

    // ---- Yl: restage via smem (reuse X region; all mma reads done), fp16 out ----
    constexpr int LDE = DOUT + 4;
    float* sEp = reinterpret_cast<float*>(smem);   // [128][LDE] fp32, fits in X region
    __syncthreads();
    #pragma unroll
    for (int mf = 0; mf < MFRAG; mf++)
        #pragma unroll
        for (int nf = 0; nf < 4; nf++)
            wmma::store_matrix_sync(&sEp[(mbase + mf * 16) * LDE + nbase + nf * 16],
                                    accl[mf][nf], LDE, wmma::mem_row_major);
    __syncthreads();
    {
        constexpr int C4 = DOUT / 4;
        for (int i = t; i < 128 * C4; i += 256) {
            int r = i / C4, c4 = i % C4;
            int gr = row0 + r;
            if (gr < N_NODES) {
                float4 v = *reinterpret_cast<const float4*>(&sEp[r * LDE + c4 * 4]);
                __half2 h0 = __floats2half2_rn(v.x, v.y);
                __half2 h1 = __floats2half2_rn(v.z, v.w);
                uint2 packed;
                packed.x = *reinterpret_cast<unsigned*>(&h0);
                packed.y = *reinterpret_cast<unsigned*>(&h1);
                *reinterpret_cast<uint2*>(Yl + (size_t)gr * DOUT + c4 * 4) = packed;
            }
        }
    }
}

// ---------------------------------------------------------------------------
// Gather (fp16 source): agg[n] = sum_{s in N(n)} yl[s]   (128 ch, warp/node)
// ---------------------------------------------------------------------------
__device__ __forceinline__ void acc_h4(float4& acc, uint2 raw) {
    __half2 p0 = *reinterpret_cast<__half2*>(&raw.x);
    __half2 p1 = *reinterpret_cast<__half2*>(&raw.y);
    float2 f0 = __half22float2(p0);
    float2 f1 = __half22float2(p1);
    acc.x += f0.x; acc.y += f0.y; acc.z += f1.x; acc.w += f1.y;
}

__global__ __launch_bounds__(256) void gather128_h_kernel(
    const __half* __restrict__ yl,
    const int* __restrict__ csr, const int* __restrict__ off,
    const int* __restrict__ cnt, float* __restrict__ agg)
{
    int warp = (blockIdx.x * 256 + threadIdx.x) >> 5;
    int lane = threadIdx.x & 31;
    if (warp >= N_NODES) return;

    const int c = cnt[warp];
    const int o = off[warp];
    const uint2* __restrict__ yl2 = reinterpret_cast<const uint2*>(yl);

    float4 acc = make_float4(0.f, 0.f, 0.f, 0.f);
    int j = 0;
    for (; j + 4 <= c; j += 4) {
        int s0 = csr[o + j + 0];
        int s1 = csr[o + j + 1];
        int s2 = csr[o + j + 2];
        int s3 = csr[o + j + 3];
        uint2 a0 = yl2[(size_t)s0 * 32 + lane];
        uint2 a1 = yl2[(size_t)s1 * 32 + lane];
        uint2 a2 = yl2[(size_t)s2 * 32 + lane];
        uint2 a3 = yl2[(size_t)s3 * 32 + lane];
        acc_h4(acc, a0); acc_h4(acc, a1); acc_h4(acc, a2); acc_h4(acc, a3);
    }
    for (; j < c; j++) {
        int s = csr[o + j];
        acc_h4(acc, yl2[(size_t)s * 32 + lane]);
    }
    reinterpret_cast<float4*>(agg)[(size_t)warp * 32 + lane] = acc;
}

// 64-ch gather with FUSED final combine: out = agg/max(deg,1) + yr + b
__global__ __launch_bounds__(256) void gather64_fused_kernel(
    const __half* __restrict__ yl, const float* __restrict__ yr,
    const float* __restrict__ b,
    const int* __restrict__ csr, const int* __restrict__ off,
    const int* __restrict__ cnt, float* __restrict__ out)
{
    int node = (blockIdx.x * 256 + threadIdx.x) >> 4;
    int sub  = threadIdx.x & 15;
    if (node >= N_NODES) return;

    const int c = cnt[node];
    const int o = off[node];
    const uint2* __restrict__ yl2 = reinterpret_cast<const uint2*>(yl);

    float4 acc = make_float4(0.f, 0.f, 0.f, 0.f);
    int j = 0;
    for (; j + 4 <= c; j += 4) {
        int s0 = csr[o + j + 0];
        int s1 = csr[o + j + 1];
        int s2 = csr[o + j + 2];
        int s3 = csr[o + j + 3];
        uint2 a0 = yl2[(size_t)s0 * 16 + sub];
        uint2 a1 = yl2[(size_t)s1 * 16 + sub];
        uint2 a2 = yl2[(size_t)s2 * 16 + sub];
        uint2 a3 = yl2[(size_t)s3 * 16 + sub];
        acc_h4(acc, a0); acc_h4(acc, a1); acc_h4(acc, a2); acc_h4(acc, a3);
    }
    for (; j < c; j++) {
        int s = csr[o + j];
        acc_h4(acc, yl2[(size_t)s * 16 + sub]);
    }

    float dinv = 1.0f / fmaxf((float)c, 1.0f);
    float4 yv = reinterpret_cast<const float4*>(yr)[(size_t)node * 16 + sub];
    float4 bb = reinterpret_cast<const float4*>(b)[sub];
    float4 o4;
    o4.x = acc.x * dinv + yv.x + bb.x;
    o4.y = acc.y * dinv + yv.y + bb.y;
    o4.z = acc.z * dinv + yv.z + bb.z;
    o4.w = acc.w * dinv + yv.w + bb.w;
    reinterpret_cast<float4*>(out)[(size_t)node * 16 + sub] = o4;
}

// ---------------------------------------------------------------------------
extern "C" void kernel_launch(void* const* d_in, const int* in_sizes, int n_in,
                              void* d_out, int out_size)
{
    const float* x   = (const float*)d_in[0];
    const void*  ei  = d_in[1];
    const float* Wl0 = (const float*)d_in[2];
    const float* Wr0 = (const float*)d_in[3];
    const float* b0  = (const float*)d_in[4];
    const float* Wl1 = (const float*)d_in[5];
    const float* Wr1 = (const float*)d_in[6];
    const float* b1  = (const float*)d_in[7];
    const float* Wl2 = (const float*)d_in[8];
    const float* Wr2 = (const float*)d_in[9];
    const float* b2  = (const float*)d_in[10];
    float* out = (float*)d_out;

    const int SMEM_X    = 128 * LDXS * 2 * (int)sizeof(__nv_bfloat16);               // 69632
    const int SMEM_128  = SMEM_X + 4 * 128 * (128 + 8) * (int)sizeof(__nv_bfloat16); // 208896
    const int SMEM_64   = SMEM_X + 4 * 128 * (64 + 8)  * (int)sizeof(__nv_bfloat16); // 143360

    static __half *p_ylh = nullptr;
    static float *p_yr = nullptr, *p_A = nullptr, *p_B = nullptr;
    static int *p_cnt = nullptr, *p_off = nullptr, *p_cur = nullptr, *p_csr = nullptr, *p_bsum = nullptr;
    static __nv_bfloat16 *p_whi = nullptr, *p_wlo = nullptr;
    static cudaStream_t s_aux = nullptr;
    static cudaEvent_t ev[4];
    if (!p_yr) {
        cudaGetSymbolAddress((void**)&p_ylh,  g_ylh);
        cudaGetSymbolAddress((void**)&p_yr,   g_yr);
        cudaGetSymbolAddress((void**)&p_A,    g_bufA);
        cudaGetSymbolAddress((void**)&p_B,    g_bufB);
        cudaGetSymbolAddress((void**)&p_cnt,  g_cnt);
        cudaGetSymbolAddress((void**)&p_off,  g_off);
        cudaGetSymbolAddress((void**)&p_cur,  g_cur);
        cudaGetSymbolAddress((void**)&p_csr,  g_csr);
        cudaGetSymbolAddress((void**)&p_bsum, g_bsum);
        cudaGetSymbolAddress((void**)&p_whi,  g_whi);
        cudaGetSymbolAddress((void**)&p_wlo,  g_wlo);
        cudaStreamCreateWithFlags(&s_aux, cudaStreamNonBlocking);
        for (int i = 0; i < 4; i++)
            cudaEventCreateWithFlags(&ev[i], cudaEventDisableTiming);
        cudaFuncSetAttribute(gemm_dual_bf16<128, false>,
                             cudaFuncAttributeMaxDynamicSharedMemorySize, SMEM_128);
        cudaFuncSetAttribute(gemm_dual_bf16<128, true>,
                             cudaFuncAttributeMaxDynamicSharedMemorySize, SMEM_128);
        cudaFuncSetAttribute(gemm_dual_bf16<64, true>,
                             cudaFuncAttributeMaxDynamicSharedMemorySize, SMEM_64);
    }

    const int NB_GEMM  = (N_NODES + 127) / 128;          // 782
    const int NB_SCAN  = (N_NODES + 1023) / 1024;
    const int NB_EDGE  = (N_EDGES + 255) / 256;
    const int NB_G128  = (N_NODES * 32 + 255) / 256;
    const int NB_G64   = (N_NODES * 16 + 255) / 256;

    // Fork aux stream: CSR build overlaps wsplit + GEMM0.
    cudaEventRecord(ev[0], 0);
    cudaStreamWaitEvent(s_aux, ev[0], 0);
    detect_kernel<<<1, 1, 0, s_aux>>>(ei);
    zero_int_kernel<<<(N_NODES + 255) / 256, 256, 0, s_aux>>>(p_cnt, N_NODES);
    hist_kernel<<<NB_EDGE, 256, 0, s_aux>>>(ei, p_cnt);
    blockreduce_kernel<<<NB_SCAN, 256, 0, s_aux>>>(p_cnt, p_bsum);
    scanpart_kernel<<<1, 32, 0, s_aux>>>(p_bsum, NB_SCAN);
    scanfinal_kernel<<<NB_SCAN, 256, 0, s_aux>>>(p_cnt, p_bsum, p_off, p_cur);
    fill_kernel<<<NB_EDGE, 256, 0, s_aux>>>(ei, p_cur, p_csr);
    cudaEventRecord(ev[1], s_aux);

    // Weight splits (main stream, tiny)
    wsplit_kernel<<<64, 256>>>(Wl0, p_whi + 0 * 16384, p_wlo + 0 * 16384, 16384);
    wsplit_kernel<<<64, 256>>>(Wr0, p_whi + 1 * 16384, p_wlo + 1 * 16384, 16384);
    wsplit_kernel<<<64, 256>>>(Wl1, p_whi + 2 * 16384, p_wlo + 2 * 16384, 16384);
    wsplit_kernel<<<64, 256>>>(Wr1, p_whi + 3 * 16384, p_wlo + 3 * 16384, 16384);
    wsplit_kernel<<<32, 256>>>(Wl2, p_whi + 4 * 16384, p_wlo + 4 * 16384, 8192);
    wsplit_kernel<<<32, 256>>>(Wr2, p_whi + 5 * 16384, p_wlo + 5 * 16384, 8192);

    // ---- Layer 0 ----
    gemm_dual_bf16<128, false><<<NB_GEMM, 256, SMEM_128>>>(
        x, nullptr, nullptr, nullptr, nullptr,
        p_whi + 0 * 16384, p_wlo + 0 * 16384, p_whi + 1 * 16384, p_wlo + 1 * 16384,
        p_ylh, p_yr);
    cudaStreamWaitEvent(0, ev[1], 0);   // CSR ready before gather
    gather128_h_kernel<<<NB_G128, 256>>>(p_ylh, p_csr, p_off, p_cnt, p_A);

    // ---- Layer 1 ----
    gemm_dual_bf16<128, true><<<NB_GEMM, 256, SMEM_128>>>(
        nullptr, p_A, p_yr, p_cnt, b0,
        p_whi + 2 * 16384, p_wlo + 2 * 16384, p_whi + 3 * 16384, p_wlo + 3 * 16384,
        p_ylh, p_yr);
    gather128_h_kernel<<<NB_G128, 256>>>(p_ylh, p_csr, p_off, p_cnt, p_B);

    // ---- Layer 2 (64 ch; gather fused with final combine -> d_out) ----
    gemm_dual_bf16<64, true><<<NB_GEMM, 256, SMEM_64>>>(
        nullptr, p_B, p_yr, p_cnt, b1,
        p_whi + 4 * 16384, p_wlo + 4 * 16384, p_whi + 5 * 16384, p_wlo + 5 * 16384,
        p_ylh, p_yr);
    gather64_fused_kernel<<<NB_G64, 256>>>(p_ylh, p_yr, b2, p_csr, p_off, p_cnt, out);
}

// round 12
// speedup vs baseline: 1.4126x; 1.0809x over previous
#include <cuda_runtime.h>
#include <cuda_bf16.h>
#include <cuda_fp16.h>
#include <mma.h>
#include <cstdint>

using namespace nvcuda;

// ---------------------------------------------------------------------------
// GraphSAGE 3-layer. Transform-then-aggregate + CSR gather (R10 structure).
// GEMMs: bf16 Markidis split on wmma tensor cores (tcgen05 unreachable:
// harness ptxas targets sm_103, not sm_103a).
// R12: 512-thread GEMM blocks (16 warps, 2x latency hiding), W split fp32->
// bf16 hi/lo in-kernel (wsplit kernels deleted).
// ---------------------------------------------------------------------------

#define N_NODES 100000
#define N_EDGES 1600000
#define LDXS 136   // X smem leading dim (bf16 elems)

__device__ __half g_ylh[(size_t)N_NODES * 128];
__device__ float  g_yr[(size_t)N_NODES * 128];
__device__ float  g_bufA[(size_t)N_NODES * 128];   // agg
__device__ float  g_bufB[(size_t)N_NODES * 128];   // agg
__device__ int    g_cnt[N_NODES];
__device__ int    g_off[N_NODES];
__device__ int    g_cur[N_NODES];
__device__ int    g_csr[N_EDGES];
__device__ int    g_bsum[128];
__device__ int    g_is64;

// --------------------------- edge dtype probe ------------------------------
__global__ void detect_kernel(const void* ei) {
    const long long* e64 = (const long long*)ei;
    int is64 = 1;
    for (int i = 0; i < 64; i++) {
        long long v = e64[i];
        if (v < 0 || v >= N_NODES) { is64 = 0; break; }
    }
    g_is64 = is64;
}

__device__ __forceinline__ int load_idx(const void* ei, long long pos) {
    if (g_is64) return (int)((const long long*)ei)[pos];
    return ((const int*)ei)[pos];
}

// ------------------------------- CSR build ---------------------------------
__global__ void zero_int_kernel(int* __restrict__ p, int n) {
    int i = blockIdx.x * blockDim.x + threadIdx.x;
    if (i < n) p[i] = 0;
}

__global__ void hist_kernel(const void* __restrict__ ei, int* __restrict__ cnt) {
    int e = blockIdx.x * blockDim.x + threadIdx.x;
    if (e < N_EDGES) {
        int d = load_idx(ei, (long long)N_EDGES + e);
        if ((unsigned)d < N_NODES) atomicAdd(&cnt[d], 1);
    }
}

__global__ void blockreduce_kernel(const int* __restrict__ cnt, int* __restrict__ bsum) {
    __shared__ int sm[256];
    int b = blockIdx.x, t = threadIdx.x;
    int base = b * 1024 + t * 4;
    int s = 0;
    #pragma unroll
    for (int i = 0; i < 4; i++) {
        int idx = base + i;
        if (idx < N_NODES) s += cnt[idx];
    }
    sm[t] = s; __syncthreads();
    for (int st = 128; st > 0; st >>= 1) {
        if (t < st) sm[t] += sm[t + st];
        __syncthreads();
    }
    if (t == 0) bsum[b] = sm[0];
}

__global__ void scanpart_kernel(int* __restrict__ bsum, int nb) {
    if (threadIdx.x == 0) {
        int acc = 0;
        for (int i = 0; i < nb; i++) { int v = bsum[i]; bsum[i] = acc; acc += v; }
    }
}

__global__ void scanfinal_kernel(const int* __restrict__ cnt, const int* __restrict__ bsum,
                                 int* __restrict__ off, int* __restrict__ cur) {
    __shared__ int sm[256];
    int b = blockIdx.x, t = threadIdx.x;
    int base = b * 1024 + t * 4;
    int v[4]; int s = 0;
    #pragma unroll
    for (int i = 0; i < 4; i++) {
        int idx = base + i;
        v[i] = (idx < N_NODES) ? cnt[idx] : 0;
        s += v[i];
    }
    sm[t] = s; __syncthreads();
    for (int st = 1; st < 256; st <<= 1) {
        int x = (t >= st) ? sm[t - st] : 0;
        __syncthreads();
        sm[t] += x;
        __syncthreads();
    }
    int run = sm[t] - s + bsum[b];
    #pragma unroll
    for (int i = 0; i < 4; i++) {
        int idx = base + i;
        if (idx < N_NODES) { off[idx] = run; cur[idx] = run; }
        run += v[i];
    }
}

__global__ void fill_kernel(const void* __restrict__ ei, int* __restrict__ cur,
                            int* __restrict__ csr) {
    int e = blockIdx.x * blockDim.x + threadIdx.x;
    if (e < N_EDGES) {
        int s = load_idx(ei, e);
        int d = load_idx(ei, (long long)N_EDGES + e);
        if ((unsigned)s < N_NODES && (unsigned)d < N_NODES) {
            int p = atomicAdd(&cur[d], 1);
            csr[p] = s;
        }
    }
}

// --------------------------- bf16 split helpers ----------------------------
__device__ __forceinline__ void split2(float a, float b, __nv_bfloat162& h2, __nv_bfloat162& l2) {
    __nv_bfloat16 ha = __float2bfloat16(a), hb = __float2bfloat16(b);
    h2 = __nv_bfloat162(ha, hb);
    l2 = __nv_bfloat162(__float2bfloat16(a - __bfloat162float(ha)),
                        __float2bfloat16(b - __bfloat162float(hb)));
}

// ---------------------------------------------------------------------------
// Dual tensor-core GEMM (512 threads): Yl(half) = H@Wl, Yr(fp32) = H@Wr
// H is X (PRO=false) or relu(agg/max(deg,1) + yrIn + bias) (PRO=true).
// X and both W matrices split to bf16 hi/lo IN-KERNEL into smem.
// Tiling: 16 warps = WM8 x WN2; each warp 16 rows x DOUT/2 cols (MFRAG=1).
// ---------------------------------------------------------------------------
template <int DOUT, bool PRO>
__global__ __launch_bounds__(512) void gemm_dual_bf16(
    const float* __restrict__ X,
    const float* __restrict__ agg, const float* __restrict__ yrIn,
    const int* __restrict__ cnt, const float* __restrict__ bias,
    const float* __restrict__ Wl, const float* __restrict__ Wr,
    __half* __restrict__ Yl, float* __restrict__ Yr)
{
    constexpr int LDW = DOUT + 8;
    extern __shared__ __nv_bfloat16 smem[];
    __nv_bfloat16* sXhi = smem;                       // [128][LDXS]
    __nv_bfloat16* sXlo = sXhi + 128 * LDXS;          // [128][LDXS]
    __nv_bfloat16* sWlh = sXlo + 128 * LDXS;          // [128][LDW]
    __nv_bfloat16* sWll = sWlh + 128 * LDW;
    __nv_bfloat16* sWrh = sWll + 128 * LDW;
    __nv_bfloat16* sWrl = sWrh + 128 * LDW;

    const int row0 = blockIdx.x * 128;
    const int t = threadIdx.x;

    // ---- stage + split W (fp32 -> bf16 hi/lo), float4 granularity ----
    {
        constexpr int C4 = DOUT / 4;
        const float4* gl = reinterpret_cast<const float4*>(Wl);
        const float4* gr = reinterpret_cast<const float4*>(Wr);
        for (int i = t; i < 128 * C4; i += 512) {
            int k = i / C4, c4 = i % C4;
            int so = k * LDW + c4 * 4;
            float4 wl = gl[i];
            float4 wr = gr[i];
            __nv_bfloat162 h0, l0, h1, l1;
            split2(wl.x, wl.y, h0, l0); split2(wl.z, wl.w, h1, l1);
            *reinterpret_cast<__nv_bfloat162*>(&sWlh[so])     = h0;
            *reinterpret_cast<__nv_bfloat162*>(&sWlh[so + 2]) = h1;
            *reinterpret_cast<__nv_bfloat162*>(&sWll[so])     = l0;
            *reinterpret_cast<__nv_bfloat162*>(&sWll[so + 2]) = l1;
            split2(wr.x, wr.y, h0, l0); split2(wr.z, wr.w, h1, l1);
            *reinterpret_cast<__nv_bfloat162*>(&sWrh[so])     = h0;
            *reinterpret_cast<__nv_bfloat162*>(&sWrh[so + 2]) = h1;
            *reinterpret_cast<__nv_bfloat162*>(&sWrl[so])     = l0;
            *reinterpret_cast<__nv_bfloat162*>(&sWrl[so + 2]) = l1;
        }
    }

    // ---- prologue: build H tile, split to bf16 hi/lo ----
    for (int i = t; i < 128 * 32; i += 512) {
        int r = i >> 5, c4 = i & 31;
        int gr = row0 + r;
        float4 v = make_float4(0.f, 0.f, 0.f, 0.f);
        if (gr < N_NODES) {
            if (PRO) {
                float4 a  = reinterpret_cast<const float4*>(agg)[(size_t)gr * 32 + c4];
                float4 yv = reinterpret_cast<const float4*>(yrIn)[(size_t)gr * 32 + c4];
                float4 bb = reinterpret_cast<const float4*>(bias)[c4];
                float dinv = 1.0f / fmaxf((float)cnt[gr], 1.0f);
                v.x = fmaxf(a.x * dinv + yv.x + bb.x, 0.f);
                v.y = fmaxf(a.y * dinv + yv.y + bb.y, 0.f);
                v.z = fmaxf(a.z * dinv + yv.z + bb.z, 0.f);
                v.w = fmaxf(a.w * dinv + yv.w + bb.w, 0.f);
            } else {
                v = reinterpret_cast<const float4*>(X + (size_t)gr * 128)[c4];
            }
        }
        __nv_bfloat162 h0, l0, h1, l1;
        split2(v.x, v.y, h0, l0);
        split2(v.z, v.w, h1, l1);
        int base = r * LDXS + c4 * 4;
        *reinterpret_cast<__nv_bfloat162*>(&sXhi[base])     = h0;
        *reinterpret_cast<__nv_bfloat162*>(&sXhi[base + 2]) = h1;
        *reinterpret_cast<__nv_bfloat162*>(&sXlo[base])     = l0;
        *reinterpret_cast<__nv_bfloat162*>(&sXlo[base + 2]) = l1;
    }
    __syncthreads();

    // ---- warp tiling: 16 warps = WM8 x WN2; warp = 16 rows x (DOUT/2) cols ----
    constexpr int NF = DOUT / 32;          // n-fragments per warp (4 or 2)
    const int warp = t >> 5;
    const int wm = warp & 7;
    const int wn = warp >> 3;
    const int mbase = wm * 16;
    const int nbase = wn * (DOUT / 2);

    wmma::fragment<wmma::accumulator, 16, 16, 16, float> accl[NF], accr[NF];
    #pragma unroll
    for (int nf = 0; nf < NF; nf++) {
        wmma::fill_fragment(accl[nf], 0.0f);
        wmma::fill_fragment(accr[nf], 0.0f);
    }

    #pragma unroll
    for (int k = 0; k < 128; k += 16) {
        wmma::fragment<wmma::matrix_a, 16, 16, 16, __nv_bfloat16, wmma::row_major> ahi, alo;
        wmma::load_matrix_sync(ahi, &sXhi[mbase * LDXS + k], LDXS);
        wmma::load_matrix_sync(alo, &sXlo[mbase * LDXS + k], LDXS);
        #pragma unroll
        for (int nf = 0; nf < NF; nf++) {
            int n0 = nbase + nf * 16;
            wmma::fragment<wmma::matrix_b, 16, 16, 16, __nv_bfloat16, wmma::row_major> bhl, bll, bhr, blr;
            wmma::load_matrix_sync(bhl, &sWlh[k * LDW + n0], LDW);
            wmma::load_matrix_sync(bll, &sWll[k * LDW + n0], LDW);
            wmma::load_matrix_sync(bhr, &sWrh[k * LDW + n0], LDW);
            wmma::load_matrix_sync(blr, &sWrl[k * LDW + n0], LDW);
            wmma::mma_sync(accl[nf], ahi, bhl, accl[nf]);
            wmma::mma_sync(accl[nf], ahi, bll, accl[nf]);
            wmma::mma_sync(accl[nf], alo, bhl, accl[nf]);
            wmma::mma_sync(accr[nf], ahi, bhr, accr[nf]);
            wmma::mma_sync(accr[nf], ahi, blr, accr[nf]);
            wmma::mma_sync(accr[nf], alo, bhr, accr[nf]);
        }
    }

    // ---- Yr: direct fragment store (fp32) ----
    {
        int grow = row0 + mbase;
        if (grow < N_NODES) {
            #pragma unroll
            for (int nf = 0; nf < NF; nf++)
                wmma::store_matrix_sync(Yr + (size_t)grow * DOUT + nbase + nf * 16,
                                        accr[nf], DOUT, wmma::mem_row_major);
        }
    }

    // ---- Yl: restage via smem (reuse X region), fp16 out ----
    constexpr int LDE = DOUT + 4;
    float* sEp = reinterpret_cast<float*>(smem);   // [128][LDE] fp32 fits in X region
    __syncthreads();
    #pragma unroll
    for (int nf = 0; nf < NF; nf++)
        wmma::store_matrix_sync(&sEp[mbase * LDE + nbase + nf * 16],
                                accl[nf], LDE, wmma::mem_row_major);
    __syncthreads();
    {
        constexpr int C4 = DOUT / 4;
        for (int i = t; i < 128 * C4; i += 512) {
            int r = i / C4, c4 = i % C4;
            int gr = row0 + r;
            if (gr < N_NODES) {
                float4 v = *reinterpret_cast<const float4*>(&sEp[r * LDE + c4 * 4]);
                __half2 h0 = __floats2half2_rn(v.x, v.y);
                __half2 h1 = __floats2half2_rn(v.z, v.w);
                uint2 packed;
                packed.x = *reinterpret_cast<unsigned*>(&h0);
                packed.y = *reinterpret_cast<unsigned*>(&h1);
                *reinterpret_cast<uint2*>(Yl + (size_t)gr * DOUT + c4 * 4) = packed;
            }
        }
    }
}

// ---------------------------------------------------------------------------
// Gather (fp16 source): agg[n] = sum_{s in N(n)} yl[s]   (128 ch, warp/node)
// ---------------------------------------------------------------------------
__device__ __forceinline__ void acc_h4(float4& acc, uint2 raw) {
    __half2 p0 = *reinterpret_cast<__half2*>(&raw.x);
    __half2 p1 = *reinterpret_cast<__half2*>(&raw.y);
    float2 f0 = __half22float2(p0);
    float2 f1 = __half22float2(p1);
    acc.x += f0.x; acc.y += f0.y; acc.z += f1.x; acc.w += f1.y;
}

__global__ __launch_bounds__(256) void gather128_h_kernel(
    const __half* __restrict__ yl,
    const int* __restrict__ csr, const int* __restrict__ off,
    const int* __restrict__ cnt, float* __restrict__ agg)
{
    int warp = (blockIdx.x * 256 + threadIdx.x) >> 5;
    int lane = threadIdx.x & 31;
    if (warp >= N_NODES) return;

    const int c = cnt[warp];
    const int o = off[warp];
    const uint2* __restrict__ yl2 = reinterpret_cast<const uint2*>(yl);

    float4 acc = make_float4(0.f, 0.f, 0.f, 0.f);
    int j = 0;
    for (; j + 4 <= c; j += 4) {
        int s0 = csr[o + j + 0];
        int s1 = csr[o + j + 1];
        int s2 = csr[o + j + 2];
        int s3 = csr[o + j + 3];
        uint2 a0 = yl2[(size_t)s0 * 32 + lane];
        uint2 a1 = yl2[(size_t)s1 * 32 + lane];
        uint2 a2 = yl2[(size_t)s2 * 32 + lane];
        uint2 a3 = yl2[(size_t)s3 * 32 + lane];
        acc_h4(acc, a0); acc_h4(acc, a1); acc_h4(acc, a2); acc_h4(acc, a3);
    }
    for (; j < c; j++) {
        int s = csr[o + j];
        acc_h4(acc, yl2[(size_t)s * 32 + lane]);
    }
    reinterpret_cast<float4*>(agg)[(size_t)warp * 32 + lane] = acc;
}

// 64-ch gather with FUSED final combine: out = agg/max(deg,1) + yr + b
__global__ __launch_bounds__(256) void gather64_fused_kernel(
    const __half* __restrict__ yl, const float* __restrict__ yr,
    const float* __restrict__ b,
    const int* __restrict__ csr, const int* __restrict__ off,
    const int* __restrict__ cnt, float* __restrict__ out)
{
    int node = (blockIdx.x * 256 + threadIdx.x) >> 4;
    int sub  = threadIdx.x & 15;
    if (node >= N_NODES) return;

    const int c = cnt[node];
    const int o = off[node];
    const uint2* __restrict__ yl2 = reinterpret_cast<const uint2*>(yl);

    float4 acc = make_float4(0.f, 0.f, 0.f, 0.f);
    int j = 0;
    for (; j + 4 <= c; j += 4) {
        int s0 = csr[o + j + 0];
        int s1 = csr[o + j + 1];
        int s2 = csr[o + j + 2];
        int s3 = csr[o + j + 3];
        uint2 a0 = yl2[(size_t)s0 * 16 + sub];
        uint2 a1 = yl2[(size_t)s1 * 16 + sub];
        uint2 a2 = yl2[(size_t)s2 * 16 + sub];
        uint2 a3 = yl2[(size_t)s3 * 16 + sub];
        acc_h4(acc, a0); acc_h4(acc, a1); acc_h4(acc, a2); acc_h4(acc, a3);
    }
    for (; j < c; j++) {
        int s = csr[o + j];
        acc_h4(acc, yl2[(size_t)s * 16 + sub]);
    }

    float dinv = 1.0f / fmaxf((float)c, 1.0f);
    float4 yv = reinterpret_cast<const float4*>(yr)[(size_t)node * 16 + sub];
    float4 bb = reinterpret_cast<const float4*>(b)[sub];
    float4 o4;
    o4.x = acc.x * dinv + yv.x + bb.x;
    o4.y = acc.y * dinv + yv.y + bb.y;
    o4.z = acc.z * dinv + yv.z + bb.z;
    o4.w = acc.w * dinv + yv.w + bb.w;
    reinterpret_cast<float4*>(out)[(size_t)node * 16 + sub] = o4;
}

// ---------------------------------------------------------------------------
extern "C" void kernel_launch(void* const* d_in, const int* in_sizes, int n_in,
                              void* d_out, int out_size)
{
    const float* x   = (const float*)d_in[0];
    const void*  ei  = d_in[1];
    const float* Wl0 = (const float*)d_in[2];
    const float* Wr0 = (const float*)d_in[3];
    const float* b0  = (const float*)d_in[4];
    const float* Wl1 = (const float*)d_in[5];
    const float* Wr1 = (const float*)d_in[6];
    const float* b1  = (const float*)d_in[7];
    const float* Wl2 = (const float*)d_in[8];
    const float* Wr2 = (const float*)d_in[9];
    const float* b2  = (const float*)d_in[10];
    float* out = (float*)d_out;

    const int SMEM_X    = 128 * LDXS * 2 * (int)sizeof(__nv_bfloat16);               // 69632
    const int SMEM_128  = SMEM_X + 4 * 128 * (128 + 8) * (int)sizeof(__nv_bfloat16); // 208896
    const int SMEM_64   = SMEM_X + 4 * 128 * (64 + 8)  * (int)sizeof(__nv_bfloat16); // 143360

    static __half *p_ylh = nullptr;
    static float *p_yr = nullptr, *p_A = nullptr, *p_B = nullptr;
    static int *p_cnt = nullptr, *p_off = nullptr, *p_cur = nullptr, *p_csr = nullptr, *p_bsum = nullptr;
    static cudaStream_t s_aux = nullptr;
    static cudaEvent_t ev[4];
    if (!p_yr) {
        cudaGetSymbolAddress((void**)&p_ylh,  g_ylh);
        cudaGetSymbolAddress((void**)&p_yr,   g_yr);
        cudaGetSymbolAddress((void**)&p_A,    g_bufA);
        cudaGetSymbolAddress((void**)&p_B,    g_bufB);
        cudaGetSymbolAddress((void**)&p_cnt,  g_cnt);
        cudaGetSymbolAddress((void**)&p_off,  g_off);
        cudaGetSymbolAddress((void**)&p_cur,  g_cur);
        cudaGetSymbolAddress((void**)&p_csr,  g_csr);
        cudaGetSymbolAddress((void**)&p_bsum, g_bsum);
        cudaStreamCreateWithFlags(&s_aux, cudaStreamNonBlocking);
        for (int i = 0; i < 4; i++)
            cudaEventCreateWithFlags(&ev[i], cudaEventDisableTiming);
        cudaFuncSetAttribute(gemm_dual_bf16<128, false>,
                             cudaFuncAttributeMaxDynamicSharedMemorySize, SMEM_128);
        cudaFuncSetAttribute(gemm_dual_bf16<128, true>,
                             cudaFuncAttributeMaxDynamicSharedMemorySize, SMEM_128);
        cudaFuncSetAttribute(gemm_dual_bf16<64, true>,
                             cudaFuncAttributeMaxDynamicSharedMemorySize, SMEM_64);
    }

    const int NB_GEMM  = (N_NODES + 127) / 128;          // 782
    const int NB_SCAN  = (N_NODES + 1023) / 1024;
    const int NB_EDGE  = (N_EDGES + 255) / 256;
    const int NB_G128  = (N_NODES * 32 + 255) / 256;
    const int NB_G64   = (N_NODES * 16 + 255) / 256;

    // Fork aux stream: CSR build overlaps GEMM0.
    cudaEventRecord(ev[0], 0);
    cudaStreamWaitEvent(s_aux, ev[0], 0);
    detect_kernel<<<1, 1, 0, s_aux>>>(ei);
    zero_int_kernel<<<(N_NODES + 255) / 256, 256, 0, s_aux>>>(p_cnt, N_NODES);
    hist_kernel<<<NB_EDGE, 256, 0, s_aux>>>(ei, p_cnt);
    blockreduce_kernel<<<NB_SCAN, 256, 0, s_aux>>>(p_cnt, p_bsum);
    scanpart_kernel<<<1, 32, 0, s_aux>>>(p_bsum, NB_SCAN);
    scanfinal_kernel<<<NB_SCAN, 256, 0, s_aux>>>(p_cnt, p_bsum, p_off, p_cur);
    fill_kernel<<<NB_EDGE, 256, 0, s_aux>>>(ei, p_cur, p_csr);
    cudaEventRecord(ev[1], s_aux);

    // ---- Layer 0 ----
    gemm_dual_bf16<128, false><<<NB_GEMM, 512, SMEM_128>>>(
        x, nullptr, nullptr, nullptr, nullptr, Wl0, Wr0, p_ylh, p_yr);
    cudaStreamWaitEvent(0, ev[1], 0);   // CSR ready before gather
    gather128_h_kernel<<<NB_G128, 256>>>(p_ylh, p_csr, p_off, p_cnt, p_A);

    // ---- Layer 1 ----
    gemm_dual_bf16<128, true><<<NB_GEMM, 512, SMEM_128>>>(
        nullptr, p_A, p_yr, p_cnt, b0, Wl1, Wr1, p_ylh, p_yr);
    gather128_h_kernel<<<NB_G128, 256>>>(p_ylh, p_csr, p_off, p_cnt, p_B);

    // ---- Layer 2 (64 ch; gather fused with final combine -> d_out) ----
    gemm_dual_bf16<64, true><<<NB_GEMM, 512, SMEM_64>>>(
        nullptr, p_B, p_yr, p_cnt, b1, Wl2, Wr2, p_ylh, p_yr);
    gather64_fused_kernel<<<NB_G64, 256>>>(p_ylh, p_yr, b2, p_csr, p_off, p_cnt, out);
}

// round 13
// speedup vs baseline: 1.5268x; 1.0808x over previous
#include <cuda_runtime.h>
#include <cuda_bf16.h>
#include <cuda_fp16.h>
#include <mma.h>
#include <cstdint>

using namespace nvcuda;

// ---------------------------------------------------------------------------
// GraphSAGE 3-layer. Transform-then-aggregate + CSR gather.
// GEMMs: bf16 Markidis split on wmma tensor cores.
// R13: PERSISTENT GEMM blocks (grid=148, 1/SM): W staged+split once per block,
// loop over 128-row tiles -> kills per-block W restaging + wave-tail waste.
// ---------------------------------------------------------------------------

#define N_NODES 100000
#define N_EDGES 1600000
#define LDXS 136   // X smem leading dim (bf16 elems)
#define NSM 148

__device__ __half g_ylh[(size_t)N_NODES * 128];
__device__ float  g_yr[(size_t)N_NODES * 128];
__device__ float  g_bufA[(size_t)N_NODES * 128];   // agg
__device__ float  g_bufB[(size_t)N_NODES * 128];   // agg
__device__ int    g_cnt[N_NODES];
__device__ int    g_off[N_NODES];
__device__ int    g_cur[N_NODES];
__device__ int    g_csr[N_EDGES];
__device__ int    g_bsum[128];
__device__ int    g_is64;

// --------------------------- edge dtype probe ------------------------------
__global__ void detect_kernel(const void* ei) {
    const long long* e64 = (const long long*)ei;
    int is64 = 1;
    for (int i = 0; i < 64; i++) {
        long long v = e64[i];
        if (v < 0 || v >= N_NODES) { is64 = 0; break; }
    }
    g_is64 = is64;
}

__device__ __forceinline__ int load_idx(const void* ei, long long pos) {
    if (g_is64) return (int)((const long long*)ei)[pos];
    return ((const int*)ei)[pos];
}

// ------------------------------- CSR build ---------------------------------
__global__ void zero_int_kernel(int* __restrict__ p, int n) {
    int i = blockIdx.x * blockDim.x + threadIdx.x;
    if (i < n) p[i] = 0;
}

__global__ void hist_kernel(const void* __restrict__ ei, int* __restrict__ cnt) {
    int e = blockIdx.x * blockDim.x + threadIdx.x;
    if (e < N_EDGES) {
        int d = load_idx(ei, (long long)N_EDGES + e);
        if ((unsigned)d < N_NODES) atomicAdd(&cnt[d], 1);
    }
}

__global__ void blockreduce_kernel(const int* __restrict__ cnt, int* __restrict__ bsum) {
    __shared__ int sm[256];
    int b = blockIdx.x, t = threadIdx.x;
    int base = b * 1024 + t * 4;
    int s = 0;
    #pragma unroll
    for (int i = 0; i < 4; i++) {
        int idx = base + i;
        if (idx < N_NODES) s += cnt[idx];
    }
    sm[t] = s; __syncthreads();
    for (int st = 128; st > 0; st >>= 1) {
        if (t < st) sm[t] += sm[t + st];
        __syncthreads();
    }
    if (t == 0) bsum[b] = sm[0];
}

__global__ void scanpart_kernel(int* __restrict__ bsum, int nb) {
    if (threadIdx.x == 0) {
        int acc = 0;
        for (int i = 0; i < nb; i++) { int v = bsum[i]; bsum[i] = acc; acc += v; }
    }
}

__global__ void scanfinal_kernel(const int* __restrict__ cnt, const int* __restrict__ bsum,
                                 int* __restrict__ off, int* __restrict__ cur) {
    __shared__ int sm[256];
    int b = blockIdx.x, t = threadIdx.x;
    int base = b * 1024 + t * 4;
    int v[4]; int s = 0;
    #pragma unroll
    for (int i = 0; i < 4; i++) {
        int idx = base + i;
        v[i] = (idx < N_NODES) ? cnt[idx] : 0;
        s += v[i];
    }
    sm[t] = s; __syncthreads();
    for (int st = 1; st < 256; st <<= 1) {
        int x = (t >= st) ? sm[t - st] : 0;
        __syncthreads();
        sm[t] += x;
        __syncthreads();
    }
    int run = sm[t] - s + bsum[b];
    #pragma unroll
    for (int i = 0; i < 4; i++) {
        int idx = base + i;
        if (idx < N_NODES) { off[idx] = run; cur[idx] = run; }
        run += v[i];
    }
}

__global__ void fill_kernel(const void* __restrict__ ei, int* __restrict__ cur,
                            int* __restrict__ csr) {
    int e = blockIdx.x * blockDim.x + threadIdx.x;
    if (e < N_EDGES) {
        int s = load_idx(ei, e);
        int d = load_idx(ei, (long long)N_EDGES + e);
        if ((unsigned)s < N_NODES && (unsigned)d < N_NODES) {
            int p = atomicAdd(&cur[d], 1);
            csr[p] = s;
        }
    }
}

// --------------------------- bf16 split helpers ----------------------------
__device__ __forceinline__ void split2(float a, float b, __nv_bfloat162& h2, __nv_bfloat162& l2) {
    __nv_bfloat16 ha = __float2bfloat16(a), hb = __float2bfloat16(b);
    h2 = __nv_bfloat162(ha, hb);
    l2 = __nv_bfloat162(__float2bfloat16(a - __bfloat162float(ha)),
                        __float2bfloat16(b - __bfloat162float(hb)));
}

// ---------------------------------------------------------------------------
// PERSISTENT dual tensor-core GEMM (512 thr, grid=NSM): Yl(half)=H@Wl,
// Yr(fp32)=H@Wr. H is X (PRO=false) or relu(agg/deg + yrIn + bias) (PRO=true).
// W staged+split ONCE per block; loop over 128-row tiles.
// Tiling: 16 warps = WM8 x WN2; warp = 16 rows x DOUT/2 cols.
// ---------------------------------------------------------------------------
template <int DOUT, bool PRO>
__global__ __launch_bounds__(512) void gemm_dual_bf16(
    const float* __restrict__ X,
    const float* __restrict__ agg, const float* __restrict__ yrIn,
    const int* __restrict__ cnt, const float* __restrict__ bias,
    const float* __restrict__ Wl, const float* __restrict__ Wr,
    __half* __restrict__ Yl, float* __restrict__ Yr)
{
    constexpr int LDW = DOUT + 8;
    constexpr int NT = (N_NODES + 127) / 128;   // 782 tiles
    extern __shared__ __nv_bfloat16 smem[];
    __nv_bfloat16* sXhi = smem;                       // [128][LDXS]
    __nv_bfloat16* sXlo = sXhi + 128 * LDXS;          // [128][LDXS]
    __nv_bfloat16* sWlh = sXlo + 128 * LDXS;          // [128][LDW]
    __nv_bfloat16* sWll = sWlh + 128 * LDW;
    __nv_bfloat16* sWrh = sWll + 128 * LDW;
    __nv_bfloat16* sWrl = sWrh + 128 * LDW;

    const int t = threadIdx.x;

    // ---- stage + split W ONCE (fp32 -> bf16 hi/lo) ----
    {
        constexpr int C4 = DOUT / 4;
        const float4* gl = reinterpret_cast<const float4*>(Wl);
        const float4* gr = reinterpret_cast<const float4*>(Wr);
        for (int i = t; i < 128 * C4; i += 512) {
            int k = i / C4, c4 = i % C4;
            int so = k * LDW + c4 * 4;
            float4 wl = gl[i];
            float4 wr = gr[i];
            __nv_bfloat162 h0, l0, h1, l1;
            split2(wl.x, wl.y, h0, l0); split2(wl.z, wl.w, h1, l1);
            *reinterpret_cast<__nv_bfloat162*>(&sWlh[so])     = h0;
            *reinterpret_cast<__nv_bfloat162*>(&sWlh[so + 2]) = h1;
            *reinterpret_cast<__nv_bfloat162*>(&sWll[so])     = l0;
            *reinterpret_cast<__nv_bfloat162*>(&sWll[so + 2]) = l1;
            split2(wr.x, wr.y, h0, l0); split2(wr.z, wr.w, h1, l1);
            *reinterpret_cast<__nv_bfloat162*>(&sWrh[so])     = h0;
            *reinterpret_cast<__nv_bfloat162*>(&sWrh[so + 2]) = h1;
            *reinterpret_cast<__nv_bfloat162*>(&sWrl[so])     = l0;
            *reinterpret_cast<__nv_bfloat162*>(&sWrl[so + 2]) = l1;
        }
    }

    // warp tiling constants
    constexpr int NF = DOUT / 32;          // n-fragments per warp (4 or 2)
    const int warp = t >> 5;
    const int wm = warp & 7;
    const int wn = warp >> 3;
    const int mbase = wm * 16;
    const int nbase = wn * (DOUT / 2);

    for (int tile = blockIdx.x; tile < NT; tile += gridDim.x) {
        const int row0 = tile * 128;

        // ---- prologue: build H tile, split to bf16 hi/lo ----
        for (int i = t; i < 128 * 32; i += 512) {
            int r = i >> 5, c4 = i & 31;
            int gr = row0 + r;
            float4 v = make_float4(0.f, 0.f, 0.f, 0.f);
            if (gr < N_NODES) {
                if (PRO) {
                    float4 a  = reinterpret_cast<const float4*>(agg)[(size_t)gr * 32 + c4];
                    float4 yv = reinterpret_cast<const float4*>(yrIn)[(size_t)gr * 32 + c4];
                    float4 bb = reinterpret_cast<const float4*>(bias)[c4];
                    float dinv = 1.0f / fmaxf((float)cnt[gr], 1.0f);
                    v.x = fmaxf(a.x * dinv + yv.x + bb.x, 0.f);
                    v.y = fmaxf(a.y * dinv + yv.y + bb.y, 0.f);
                    v.z = fmaxf(a.z * dinv + yv.z + bb.z, 0.f);
                    v.w = fmaxf(a.w * dinv + yv.w + bb.w, 0.f);
                } else {
                    v = reinterpret_cast<const float4*>(X + (size_t)gr * 128)[c4];
                }
            }
            __nv_bfloat162 h0, l0, h1, l1;
            split2(v.x, v.y, h0, l0);
            split2(v.z, v.w, h1, l1);
            int base = r * LDXS + c4 * 4;
            *reinterpret_cast<__nv_bfloat162*>(&sXhi[base])     = h0;
            *reinterpret_cast<__nv_bfloat162*>(&sXhi[base + 2]) = h1;
            *reinterpret_cast<__nv_bfloat162*>(&sXlo[base])     = l0;
            *reinterpret_cast<__nv_bfloat162*>(&sXlo[base + 2]) = l1;
        }
        __syncthreads();

        wmma::fragment<wmma::accumulator, 16, 16, 16, float> accl[NF], accr[NF];
        #pragma unroll
        for (int nf = 0; nf < NF; nf++) {
            wmma::fill_fragment(accl[nf], 0.0f);
            wmma::fill_fragment(accr[nf], 0.0f);
        }

        #pragma unroll
        for (int k = 0; k < 128; k += 16) {
            wmma::fragment<wmma::matrix_a, 16, 16, 16, __nv_bfloat16, wmma::row_major> ahi, alo;
            wmma::load_matrix_sync(ahi, &sXhi[mbase * LDXS + k], LDXS);
            wmma::load_matrix_sync(alo, &sXlo[mbase * LDXS + k], LDXS);
            #pragma unroll
            for (int nf = 0; nf < NF; nf++) {
                int n0 = nbase + nf * 16;
                wmma::fragment<wmma::matrix_b, 16, 16, 16, __nv_bfloat16, wmma::row_major> bhl, bll, bhr, blr;
                wmma::load_matrix_sync(bhl, &sWlh[k * LDW + n0], LDW);
                wmma::load_matrix_sync(bll, &sWll[k * LDW + n0], LDW);
                wmma::load_matrix_sync(bhr, &sWrh[k * LDW + n0], LDW);
                wmma::load_matrix_sync(blr, &sWrl[k * LDW + n0], LDW);
                wmma::mma_sync(accl[nf], ahi, bhl, accl[nf]);
                wmma::mma_sync(accl[nf], ahi, bll, accl[nf]);
                wmma::mma_sync(accl[nf], alo, bhl, accl[nf]);
                wmma::mma_sync(accr[nf], ahi, bhr, accr[nf]);
                wmma::mma_sync(accr[nf], ahi, blr, accr[nf]);
                wmma::mma_sync(accr[nf], alo, bhr, accr[nf]);
            }
        }

        // ---- Yr: direct fragment store (fp32) ----
        {
            int grow = row0 + mbase;
            if (grow < N_NODES) {
                #pragma unroll
                for (int nf = 0; nf < NF; nf++)
                    wmma::store_matrix_sync(Yr + (size_t)grow * DOUT + nbase + nf * 16,
                                            accr[nf], DOUT, wmma::mem_row_major);
            }
        }

        // ---- Yl: restage via smem (reuse X region), fp16 out ----
        constexpr int LDE = DOUT + 4;
        float* sEp = reinterpret_cast<float*>(smem);   // [128][LDE] fp32 in X region
        __syncthreads();
        #pragma unroll
        for (int nf = 0; nf < NF; nf++)
            wmma::store_matrix_sync(&sEp[mbase * LDE + nbase + nf * 16],
                                    accl[nf], LDE, wmma::mem_row_major);
        __syncthreads();
        {
            constexpr int C4 = DOUT / 4;
            for (int i = t; i < 128 * C4; i += 512) {
                int r = i / C4, c4 = i % C4;
                int gr = row0 + r;
                if (gr < N_NODES) {
                    float4 v = *reinterpret_cast<const float4*>(&sEp[r * LDE + c4 * 4]);
                    __half2 h0 = __floats2half2_rn(v.x, v.y);
                    __half2 h1 = __floats2half2_rn(v.z, v.w);
                    uint2 packed;
                    packed.x = *reinterpret_cast<unsigned*>(&h0);
                    packed.y = *reinterpret_cast<unsigned*>(&h1);
                    *reinterpret_cast<uint2*>(Yl + (size_t)gr * DOUT + c4 * 4) = packed;
                }
            }
        }
        __syncthreads();   // sEp (X region) fully consumed before next tile
    }
}

// ---------------------------------------------------------------------------
// Gather (fp16 source): agg[n] = sum_{s in N(n)} yl[s]   (128 ch, warp/node)
// ---------------------------------------------------------------------------
__device__ __forceinline__ void acc_h4(float4& acc, uint2 raw) {
    __half2 p0 = *reinterpret_cast<__half2*>(&raw.x);
    __half2 p1 = *reinterpret_cast<__half2*>(&raw.y);
    float2 f0 = __half22float2(p0);
    float2 f1 = __half22float2(p1);
    acc.x += f0.x; acc.y += f0.y; acc.z += f1.x; acc.w += f1.y;
}

__global__ __launch_bounds__(256) void gather128_h_kernel(
    const __half* __restrict__ yl,
    const int* __restrict__ csr, const int* __restrict__ off,
    const int* __restrict__ cnt, float* __restrict__ agg)
{
    int warp = (blockIdx.x * 256 + threadIdx.x) >> 5;
    int lane = threadIdx.x & 31;
    if (warp >= N_NODES) return;

    const int c = cnt[warp];
    const int o = off[warp];
    const uint2* __restrict__ yl2 = reinterpret_cast<const uint2*>(yl);

    float4 acc = make_float4(0.f, 0.f, 0.f, 0.f);
    int j = 0;
    for (; j + 4 <= c; j += 4) {
        int s0 = csr[o + j + 0];
        int s1 = csr[o + j + 1];
        int s2 = csr[o + j + 2];
        int s3 = csr[o + j + 3];
        uint2 a0 = yl2[(size_t)s0 * 32 + lane];
        uint2 a1 = yl2[(size_t)s1 * 32 + lane];
        uint2 a2 = yl2[(size_t)s2 * 32 + lane];
        uint2 a3 = yl2[(size_t)s3 * 32 + lane];
        acc_h4(acc, a0); acc_h4(acc, a1); acc_h4(acc, a2); acc_h4(acc, a3);
    }
    for (; j < c; j++) {
        int s = csr[o + j];
        acc_h4(acc, yl2[(size_t)s * 32 + lane]);
    }
    reinterpret_cast<float4*>(agg)[(size_t)warp * 32 + lane] = acc;
}

// 64-ch gather with FUSED final combine: out = agg/max(deg,1) + yr + b
__global__ __launch_bounds__(256) void gather64_fused_kernel(
    const __half* __restrict__ yl, const float* __restrict__ yr,
    const float* __restrict__ b,
    const int* __restrict__ csr, const int* __restrict__ off,
    const int* __restrict__ cnt, float* __restrict__ out)
{
    int node = (blockIdx.x * 256 + threadIdx.x) >> 4;
    int sub  = threadIdx.x & 15;
    if (node >= N_NODES) return;

    const int c = cnt[node];
    const int o = off[node];
    const uint2* __restrict__ yl2 = reinterpret_cast<const uint2*>(yl);

    float4 acc = make_float4(0.f, 0.f, 0.f, 0.f);
    int j = 0;
    for (; j + 4 <= c; j += 4) {
        int s0 = csr[o + j + 0];
        int s1 = csr[o + j + 1];
        int s2 = csr[o + j + 2];
        int s3 = csr[o + j + 3];
        uint2 a0 = yl2[(size_t)s0 * 16 + sub];
        uint2 a1 = yl2[(size_t)s1 * 16 + sub];
        uint2 a2 = yl2[(size_t)s2 * 16 + sub];
        uint2 a3 = yl2[(size_t)s3 * 16 + sub];
        acc_h4(acc, a0); acc_h4(acc, a1); acc_h4(acc, a2); acc_h4(acc, a3);
    }
    for (; j < c; j++) {
        int s = csr[o + j];
        acc_h4(acc, yl2[(size_t)s * 16 + sub]);
    }

    float dinv = 1.0f / fmaxf((float)c, 1.0f);
    float4 yv = reinterpret_cast<const float4*>(yr)[(size_t)node * 16 + sub];
    float4 bb = reinterpret_cast<const float4*>(b)[sub];
    float4 o4;
    o4.x = acc.x * dinv + yv.x + bb.x;
    o4.y = acc.y * dinv + yv.y + bb.y;
    o4.z = acc.z * dinv + yv.z + bb.z;
    o4.w = acc.w * dinv + yv.w + bb.w;
    reinterpret_cast<float4*>(out)[(size_t)node * 16 + sub] = o4;
}

// ---------------------------------------------------------------------------
extern "C" void kernel_launch(void* const* d_in, const int* in_sizes, int n_in,
                              void* d_out, int out_size)
{
    const float* x   = (const float*)d_in[0];
    const void*  ei  = d_in[1];
    const float* Wl0 = (const float*)d_in[2];
    const float* Wr0 = (const float*)d_in[3];
    const float* b0  = (const float*)d_in[4];
    const float* Wl1 = (const float*)d_in[5];
    const float* Wr1 = (const float*)d_in[6];
    const float* b1  = (const float*)d_in[7];
    const float* Wl2 = (const float*)d_in[8];
    const float* Wr2 = (const float*)d_in[9];
    const float* b2  = (const float*)d_in[10];
    float* out = (float*)d_out;

    const int SMEM_X    = 128 * LDXS * 2 * (int)sizeof(__nv_bfloat16);               // 69632
    const int SMEM_128  = SMEM_X + 4 * 128 * (128 + 8) * (int)sizeof(__nv_bfloat16); // 208896
    const int SMEM_64   = SMEM_X + 4 * 128 * (64 + 8)  * (int)sizeof(__nv_bfloat16); // 143360

    static __half *p_ylh = nullptr;
    static float *p_yr = nullptr, *p_A = nullptr, *p_B = nullptr;
    static int *p_cnt = nullptr, *p_off = nullptr, *p_cur = nullptr, *p_csr = nullptr, *p_bsum = nullptr;
    static cudaStream_t s_aux = nullptr;
    static cudaEvent_t ev[4];
    if (!p_yr) {
        cudaGetSymbolAddress((void**)&p_ylh,  g_ylh);
        cudaGetSymbolAddress((void**)&p_yr,   g_yr);
        cudaGetSymbolAddress((void**)&p_A,    g_bufA);
        cudaGetSymbolAddress((void**)&p_B,    g_bufB);
        cudaGetSymbolAddress((void**)&p_cnt,  g_cnt);
        cudaGetSymbolAddress((void**)&p_off,  g_off);
        cudaGetSymbolAddress((void**)&p_cur,  g_cur);
        cudaGetSymbolAddress((void**)&p_csr,  g_csr);
        cudaGetSymbolAddress((void**)&p_bsum, g_bsum);
        cudaStreamCreateWithFlags(&s_aux, cudaStreamNonBlocking);
        for (int i = 0; i < 4; i++)
            cudaEventCreateWithFlags(&ev[i], cudaEventDisableTiming);
        cudaFuncSetAttribute(gemm_dual_bf16<128, false>,
                             cudaFuncAttributeMaxDynamicSharedMemorySize, SMEM_128);
        cudaFuncSetAttribute(gemm_dual_bf16<128, true>,
                             cudaFuncAttributeMaxDynamicSharedMemorySize, SMEM_128);
        cudaFuncSetAttribute(gemm_dual_bf16<64, true>,
                             cudaFuncAttributeMaxDynamicSharedMemorySize, SMEM_64);
    }

    const int NB_SCAN  = (N_NODES + 1023) / 1024;
    const int NB_EDGE  = (N_EDGES + 255) / 256;
    const int NB_G128  = (N_NODES * 32 + 255) / 256;
    const int NB_G64   = (N_NODES * 16 + 255) / 256;

    // Fork aux stream: CSR build overlaps GEMM0.
    cudaEventRecord(ev[0], 0);
    cudaStreamWaitEvent(s_aux, ev[0], 0);
    detect_kernel<<<1, 1, 0, s_aux>>>(ei);
    zero_int_kernel<<<(N_NODES + 255) / 256, 256, 0, s_aux>>>(p_cnt, N_NODES);
    hist_kernel<<<NB_EDGE, 256, 0, s_aux>>>(ei, p_cnt);
    blockreduce_kernel<<<NB_SCAN, 256, 0, s_aux>>>(p_cnt, p_bsum);
    scanpart_kernel<<<1, 32, 0, s_aux>>>(p_bsum, NB_SCAN);
    scanfinal_kernel<<<NB_SCAN, 256, 0, s_aux>>>(p_cnt, p_bsum, p_off, p_cur);
    fill_kernel<<<NB_EDGE, 256, 0, s_aux>>>(ei, p_cur, p_csr);
    cudaEventRecord(ev[1], s_aux);

    // ---- Layer 0 ----
    gemm_dual_bf16<128, false><<<NSM, 512, SMEM_128>>>(
        x, nullptr, nullptr, nullptr, nullptr, Wl0, Wr0, p_ylh, p_yr);
    cudaStreamWaitEvent(0, ev[1], 0);   // CSR ready before gather
    gather128_h_kernel<<<NB_G128, 256>>>(p_ylh, p_csr, p_off, p_cnt, p_A);

    // ---- Layer 1 ----
    gemm_dual_bf16<128, true><<<NSM, 512, SMEM_128>>>(
        nullptr, p_A, p_yr, p_cnt, b0, Wl1, Wr1, p_ylh, p_yr);
    gather128_h_kernel<<<NB_G128, 256>>>(p_ylh, p_csr, p_off, p_cnt, p_B);

    // ---- Layer 2 (64 ch; gather fused with final combine -> d_out) ----
    gemm_dual_bf16<64, true><<<NSM, 512, SMEM_64>>>(
        nullptr, p_B, p_yr, p_cnt, b1, Wl2, Wr2, p_ylh, p_yr);
    gather64_fused_kernel<<<NB_G64, 256>>>(p_ylh, p_yr, b2, p_csr, p_off, p_cnt, out);
}

// round 14
// speedup vs baseline: 1.6973x; 1.1117x over previous
#include <cuda_runtime.h>
#include <cuda_bf16.h>
#include <cuda_fp16.h>
#include <mma.h>
#include <cstdint>

using namespace nvcuda;

// ---------------------------------------------------------------------------
// GraphSAGE 3-layer. Transform-then-aggregate + CSR gather.
// GEMMs: bf16 Markidis split on wmma tensor cores, persistent blocks.
// R14: warp retile WM4 x WN4 x MFRAG2 (32 rows x DOUT/4 cols per warp):
// ldsm per k-step 18 -> 12, b-fragments reused across 2 m-fragments.
// ---------------------------------------------------------------------------

#define N_NODES 100000
#define N_EDGES 1600000
#define LDXS 136   // X smem leading dim (bf16 elems)
#define NSM 148

__device__ __half g_ylh[(size_t)N_NODES * 128];
__device__ float  g_yr[(size_t)N_NODES * 128];
__device__ float  g_bufA[(size_t)N_NODES * 128];   // agg
__device__ float  g_bufB[(size_t)N_NODES * 128];   // agg
__device__ int    g_cnt[N_NODES];
__device__ int    g_off[N_NODES];
__device__ int    g_cur[N_NODES];
__device__ int    g_csr[N_EDGES];
__device__ int    g_bsum[128];
__device__ int    g_is64;

// --------------------------- edge dtype probe ------------------------------
__global__ void detect_kernel(const void* ei) {
    const long long* e64 = (const long long*)ei;
    int is64 = 1;
    for (int i = 0; i < 64; i++) {
        long long v = e64[i];
        if (v < 0 || v >= N_NODES) { is64 = 0; break; }
    }
    g_is64 = is64;
}

__device__ __forceinline__ int load_idx(const void* ei, long long pos) {
    if (g_is64) return (int)((const long long*)ei)[pos];
    return ((const int*)ei)[pos];
}

// ------------------------------- CSR build ---------------------------------
__global__ void zero_int_kernel(int* __restrict__ p, int n) {
    int i = blockIdx.x * blockDim.x + threadIdx.x;
    if (i < n) p[i] = 0;
}

__global__ void hist_kernel(const void* __restrict__ ei, int* __restrict__ cnt) {
    int e = blockIdx.x * blockDim.x + threadIdx.x;
    if (e < N_EDGES) {
        int d = load_idx(ei, (long long)N_EDGES + e);
        if ((unsigned)d < N_NODES) atomicAdd(&cnt[d], 1);
    }
}

__global__ void blockreduce_kernel(const int* __restrict__ cnt, int* __restrict__ bsum) {
    __shared__ int sm[256];
    int b = blockIdx.x, t = threadIdx.x;
    int base = b * 1024 + t * 4;
    int s = 0;
    #pragma unroll
    for (int i = 0; i < 4; i++) {
        int idx = base + i;
        if (idx < N_NODES) s += cnt[idx];
    }
    sm[t] = s; __syncthreads();
    for (int st = 128; st > 0; st >>= 1) {
        if (t < st) sm[t] += sm[t + st];
        __syncthreads();
    }
    if (t == 0) bsum[b] = sm[0];
}

__global__ void scanpart_kernel(int* __restrict__ bsum, int nb) {
    if (threadIdx.x == 0) {
        int acc = 0;
        for (int i = 0; i < nb; i++) { int v = bsum[i]; bsum[i] = acc; acc += v; }
    }
}

__global__ void scanfinal_kernel(const int* __restrict__ cnt, const int* __restrict__ bsum,
                                 int* __restrict__ off, int* __restrict__ cur) {
    __shared__ int sm[256];
    int b = blockIdx.x, t = threadIdx.x;
    int base = b * 1024 + t * 4;
    int v[4]; int s = 0;
    #pragma unroll
    for (int i = 0; i < 4; i++) {
        int idx = base + i;
        v[i] = (idx < N_NODES) ? cnt[idx] : 0;
        s += v[i];
    }
    sm[t] = s; __syncthreads();
    for (int st = 1; st < 256; st <<= 1) {
        int x = (t >= st) ? sm[t - st] : 0;
        __syncthreads();
        sm[t] += x;
        __syncthreads();
    }
    int run = sm[t] - s + bsum[b];
    #pragma unroll
    for (int i = 0; i < 4; i++) {
        int idx = base + i;
        if (idx < N_NODES) { off[idx] = run; cur[idx] = run; }
        run += v[i];
    }
}

__global__ void fill_kernel(const void* __restrict__ ei, int* __restrict__ cur,
                            int* __restrict__ csr) {
    int e = blockIdx.x * blockDim.x + threadIdx.x;
    if (e < N_EDGES) {
        int s = load_idx(ei, e);
        int d = load_idx(ei, (long long)N_EDGES + e);
        if ((unsigned)s < N_NODES && (unsigned)d < N_NODES) {
            int p = atomicAdd(&cur[d], 1);
            csr[p] = s;
        }
    }
}

// --------------------------- bf16 split helpers ----------------------------
__device__ __forceinline__ void split2(float a, float b, __nv_bfloat162& h2, __nv_bfloat162& l2) {
    __nv_bfloat16 ha = __float2bfloat16(a), hb = __float2bfloat16(b);
    h2 = __nv_bfloat162(ha, hb);
    l2 = __nv_bfloat162(__float2bfloat16(a - __bfloat162float(ha)),
                        __float2bfloat16(b - __bfloat162float(hb)));
}

// ---------------------------------------------------------------------------
// PERSISTENT dual tensor-core GEMM (512 thr, grid=NSM): Yl(half)=H@Wl,
// Yr(fp32)=H@Wr. H is X (PRO=false) or relu(agg/deg + yrIn + bias) (PRO=true).
// W staged+split ONCE per block; loop over 128-row tiles.
// Tiling: 16 warps = WM4 x WN4; warp = 32 rows (MFRAG=2) x DOUT/4 cols.
// ---------------------------------------------------------------------------
template <int DOUT, bool PRO>
__global__ __launch_bounds__(512) void gemm_dual_bf16(
    const float* __restrict__ X,
    const float* __restrict__ agg, const float* __restrict__ yrIn,
    const int* __restrict__ cnt, const float* __restrict__ bias,
    const float* __restrict__ Wl, const float* __restrict__ Wr,
    __half* __restrict__ Yl, float* __restrict__ Yr)
{
    constexpr int LDW = DOUT + 8;
    constexpr int NT = (N_NODES + 127) / 128;   // 782 tiles
    extern __shared__ __nv_bfloat16 smem[];
    __nv_bfloat16* sXhi = smem;                       // [128][LDXS]
    __nv_bfloat16* sXlo = sXhi + 128 * LDXS;          // [128][LDXS]
    __nv_bfloat16* sWlh = sXlo + 128 * LDXS;          // [128][LDW]
    __nv_bfloat16* sWll = sWlh + 128 * LDW;
    __nv_bfloat16* sWrh = sWll + 128 * LDW;
    __nv_bfloat16* sWrl = sWrh + 128 * LDW;

    const int t = threadIdx.x;

    // ---- stage + split W ONCE (fp32 -> bf16 hi/lo) ----
    {
        constexpr int C4 = DOUT / 4;
        const float4* gl = reinterpret_cast<const float4*>(Wl);
        const float4* gr = reinterpret_cast<const float4*>(Wr);
        for (int i = t; i < 128 * C4; i += 512) {
            int k = i / C4, c4 = i % C4;
            int so = k * LDW + c4 * 4;
            float4 wl = gl[i];
            float4 wr = gr[i];
            __nv_bfloat162 h0, l0, h1, l1;
            split2(wl.x, wl.y, h0, l0); split2(wl.z, wl.w, h1, l1);
            *reinterpret_cast<__nv_bfloat162*>(&sWlh[so])     = h0;
            *reinterpret_cast<__nv_bfloat162*>(&sWlh[so + 2]) = h1;
            *reinterpret_cast<__nv_bfloat162*>(&sWll[so])     = l0;
            *reinterpret_cast<__nv_bfloat162*>(&sWll[so + 2]) = l1;
            split2(wr.x, wr.y, h0, l0); split2(wr.z, wr.w, h1, l1);
            *reinterpret_cast<__nv_bfloat162*>(&sWrh[so])     = h0;
            *reinterpret_cast<__nv_bfloat162*>(&sWrh[so + 2]) = h1;
            *reinterpret_cast<__nv_bfloat162*>(&sWrl[so])     = l0;
            *reinterpret_cast<__nv_bfloat162*>(&sWrl[so + 2]) = l1;
        }
    }

    // warp tiling constants: WM4 x WN4, MFRAG=2
    constexpr int NF = DOUT / 64;          // n-fragments per warp (2 or 1)
    const int warp = t >> 5;
    const int wm = warp & 3;
    const int wn = warp >> 2;
    const int mbase = wm * 32;             // 32 rows per warp
    const int nbase = wn * (DOUT / 4);     // DOUT/4 cols per warp

    for (int tile = blockIdx.x; tile < NT; tile += gridDim.x) {
        const int row0 = tile * 128;

        // ---- prologue: build H tile, split to bf16 hi/lo ----
        for (int i = t; i < 128 * 32; i += 512) {
            int r = i >> 5, c4 = i & 31;
            int gr = row0 + r;
            float4 v = make_float4(0.f, 0.f, 0.f, 0.f);
            if (gr < N_NODES) {
                if (PRO) {
                    float4 a  = reinterpret_cast<const float4*>(agg)[(size_t)gr * 32 + c4];
                    float4 yv = reinterpret_cast<const float4*>(yrIn)[(size_t)gr * 32 + c4];
                    float4 bb = reinterpret_cast<const float4*>(bias)[c4];
                    float dinv = 1.0f / fmaxf((float)cnt[gr], 1.0f);
                    v.x = fmaxf(a.x * dinv + yv.x + bb.x, 0.f);
                    v.y = fmaxf(a.y * dinv + yv.y + bb.y, 0.f);
                    v.z = fmaxf(a.z * dinv + yv.z + bb.z, 0.f);
                    v.w = fmaxf(a.w * dinv + yv.w + bb.w, 0.f);
                } else {
                    v = reinterpret_cast<const float4*>(X + (size_t)gr * 128)[c4];
                }
            }
            __nv_bfloat162 h0, l0, h1, l1;
            split2(v.x, v.y, h0, l0);
            split2(v.z, v.w, h1, l1);
            int base = r * LDXS + c4 * 4;
            *reinterpret_cast<__nv_bfloat162*>(&sXhi[base])     = h0;
            *reinterpret_cast<__nv_bfloat162*>(&sXhi[base + 2]) = h1;
            *reinterpret_cast<__nv_bfloat162*>(&sXlo[base])     = l0;
            *reinterpret_cast<__nv_bfloat162*>(&sXlo[base + 2]) = l1;
        }
        __syncthreads();

        wmma::fragment<wmma::accumulator, 16, 16, 16, float> accl[2][NF], accr[2][NF];
        #pragma unroll
        for (int mf = 0; mf < 2; mf++)
            #pragma unroll
            for (int nf = 0; nf < NF; nf++) {
                wmma::fill_fragment(accl[mf][nf], 0.0f);
                wmma::fill_fragment(accr[mf][nf], 0.0f);
            }

        #pragma unroll
        for (int k = 0; k < 128; k += 16) {
            wmma::fragment<wmma::matrix_a, 16, 16, 16, __nv_bfloat16, wmma::row_major> ahi[2], alo[2];
            #pragma unroll
            for (int mf = 0; mf < 2; mf++) {
                wmma::load_matrix_sync(ahi[mf], &sXhi[(mbase + mf * 16) * LDXS + k], LDXS);
                wmma::load_matrix_sync(alo[mf], &sXlo[(mbase + mf * 16) * LDXS + k], LDXS);
            }
            #pragma unroll
            for (int nf = 0; nf < NF; nf++) {
                int n0 = nbase + nf * 16;
                wmma::fragment<wmma::matrix_b, 16, 16, 16, __nv_bfloat16, wmma::row_major> bhl, bll, bhr, blr;
                wmma::load_matrix_sync(bhl, &sWlh[k * LDW + n0], LDW);
                wmma::load_matrix_sync(bll, &sWll[k * LDW + n0], LDW);
                wmma::load_matrix_sync(bhr, &sWrh[k * LDW + n0], LDW);
                wmma::load_matrix_sync(blr, &sWrl[k * LDW + n0], LDW);
                #pragma unroll
                for (int mf = 0; mf < 2; mf++) {
                    wmma::mma_sync(accl[mf][nf], ahi[mf], bhl, accl[mf][nf]);
                    wmma::mma_sync(accl[mf][nf], ahi[mf], bll, accl[mf][nf]);
                    wmma::mma_sync(accl[mf][nf], alo[mf], bhl, accl[mf][nf]);
                    wmma::mma_sync(accr[mf][nf], ahi[mf], bhr, accr[mf][nf]);
                    wmma::mma_sync(accr[mf][nf], ahi[mf], blr, accr[mf][nf]);
                    wmma::mma_sync(accr[mf][nf], alo[mf], bhr, accr[mf][nf]);
                }
            }
        }

        // ---- Yr: direct fragment store (fp32) ----
        #pragma unroll
        for (int mf = 0; mf < 2; mf++) {
            int grow = row0 + mbase + mf * 16;
            if (grow < N_NODES) {
                #pragma unroll
                for (int nf = 0; nf < NF; nf++)
                    wmma::store_matrix_sync(Yr + (size_t)grow * DOUT + nbase + nf * 16,
                                            accr[mf][nf], DOUT, wmma::mem_row_major);
            }
        }

        // ---- Yl: restage via smem (reuse X region), fp16 out ----
        constexpr int LDE = DOUT + 4;
        float* sEp = reinterpret_cast<float*>(smem);   // [128][LDE] fp32 in X region
        __syncthreads();
        #pragma unroll
        for (int mf = 0; mf < 2; mf++)
            #pragma unroll
            for (int nf = 0; nf < NF; nf++)
                wmma::store_matrix_sync(&sEp[(mbase + mf * 16) * LDE + nbase + nf * 16],
                                        accl[mf][nf], LDE, wmma::mem_row_major);
        __syncthreads();
        {
            constexpr int C4 = DOUT / 4;
            for (int i = t; i < 128 * C4; i += 512) {
                int r = i / C4, c4 = i % C4;
                int gr = row0 + r;
                if (gr < N_NODES) {
                    float4 v = *reinterpret_cast<const float4*>(&sEp[r * LDE + c4 * 4]);
                    __half2 h0 = __floats2half2_rn(v.x, v.y);
                    __half2 h1 = __floats2half2_rn(v.z, v.w);
                    uint2 packed;
                    packed.x = *reinterpret_cast<unsigned*>(&h0);
                    packed.y = *reinterpret_cast<unsigned*>(&h1);
                    *reinterpret_cast<uint2*>(Yl + (size_t)gr * DOUT + c4 * 4) = packed;
                }
            }
        }
        __syncthreads();   // sEp (X region) fully consumed before next tile
    }
}

// ---------------------------------------------------------------------------
// Gather (fp16 source): agg[n] = sum_{s in N(n)} yl[s]   (128 ch, warp/node)
// ---------------------------------------------------------------------------
__device__ __forceinline__ void acc_h4(float4& acc, uint2 raw) {
    __half2 p0 = *reinterpret_cast<__half2*>(&raw.x);
    __half2 p1 = *reinterpret_cast<__half2*>(&raw.y);
    float2 f0 = __half22float2(p0);
    float2 f1 = __half22float2(p1);
    acc.x += f0.x; acc.y += f0.y; acc.z += f1.x; acc.w += f1.y;
}

__global__ __launch_bounds__(256) void gather128_h_kernel(
    const __half* __restrict__ yl,
    const int* __restrict__ csr, const int* __restrict__ off,
    const int* __restrict__ cnt, float* __restrict__ agg)
{
    int warp = (blockIdx.x * 256 + threadIdx.x) >> 5;
    int lane = threadIdx.x & 31;
    if (warp >= N_NODES) return;

    const int c = cnt[warp];
    const int o = off[warp];
    const uint2* __restrict__ yl2 = reinterpret_cast<const uint2*>(yl);

    float4 acc = make_float4(0.f, 0.f, 0.f, 0.f);
    int j = 0;
    for (; j + 4 <= c; j += 4) {
        int s0 = csr[o + j + 0];
        int s1 = csr[o + j + 1];
        int s2 = csr[o + j + 2];
        int s3 = csr[o + j + 3];
        uint2 a0 = yl2[(size_t)s0 * 32 + lane];
        uint2 a1 = yl2[(size_t)s1 * 32 + lane];
        uint2 a2 = yl2[(size_t)s2 * 32 + lane];
        uint2 a3 = yl2[(size_t)s3 * 32 + lane];
        acc_h4(acc, a0); acc_h4(acc, a1); acc_h4(acc, a2); acc_h4(acc, a3);
    }
    for (; j < c; j++) {
        int s = csr[o + j];
        acc_h4(acc, yl2[(size_t)s * 32 + lane]);
    }
    reinterpret_cast<float4*>(agg)[(size_t)warp * 32 + lane] = acc;
}

// 64-ch gather with FUSED final combine: out = agg/max(deg,1) + yr + b
__global__ __launch_bounds__(256) void gather64_fused_kernel(
    const __half* __restrict__ yl, const float* __restrict__ yr,
    const float* __restrict__ b,
    const int* __restrict__ csr, const int* __restrict__ off,
    const int* __restrict__ cnt, float* __restrict__ out)
{
    int node = (blockIdx.x * 256 + threadIdx.x) >> 4;
    int sub  = threadIdx.x & 15;
    if (node >= N_NODES) return;

    const int c = cnt[node];
    const int o = off[node];
    const uint2* __restrict__ yl2 = reinterpret_cast<const uint2*>(yl);

    float4 acc = make_float4(0.f, 0.f, 0.f, 0.f);
    int j = 0;
    for (; j + 4 <= c; j += 4) {
        int s0 = csr[o + j + 0];
        int s1 = csr[o + j + 1];
        int s2 = csr[o + j + 2];
        int s3 = csr[o + j + 3];
        uint2 a0 = yl2[(size_t)s0 * 16 + sub];
        uint2 a1 = yl2[(size_t)s1 * 16 + sub];
        uint2 a2 = yl2[(size_t)s2 * 16 + sub];
        uint2 a3 = yl2[(size_t)s3 * 16 + sub];
        acc_h4(acc, a0); acc_h4(acc, a1); acc_h4(acc, a2); acc_h4(acc, a3);
    }
    for (; j < c; j++) {
        int s = csr[o + j];
        acc_h4(acc, yl2[(size_t)s * 16 + sub]);
    }

    float dinv = 1.0f / fmaxf((float)c, 1.0f);
    float4 yv = reinterpret_cast<const float4*>(yr)[(size_t)node * 16 + sub];
    float4 bb = reinterpret_cast<const float4*>(b)[sub];
    float4 o4;
    o4.x = acc.x * dinv + yv.x + bb.x;
    o4.y = acc.y * dinv + yv.y + bb.y;
    o4.z = acc.z * dinv + yv.z + bb.z;
    o4.w = acc.w * dinv + yv.w + bb.w;
    reinterpret_cast<float4*>(out)[(size_t)node * 16 + sub] = o4;
}

// ---------------------------------------------------------------------------
extern "C" void kernel_launch(void* const* d_in, const int* in_sizes, int n_in,
                              void* d_out, int out_size)
{
    const float* x   = (const float*)d_in[0];
    const void*  ei  = d_in[1];
    const float* Wl0 = (const float*)d_in[2];
    const float* Wr0 = (const float*)d_in[3];
    const float* b0  = (const float*)d_in[4];
    const float* Wl1 = (const float*)d_in[5];
    const float* Wr1 = (const float*)d_in[6];
    const float* b1  = (const float*)d_in[7];
    const float* Wl2 = (const float*)d_in[8];
    const float* Wr2 = (const float*)d_in[9];
    const float* b2  = (const float*)d_in[10];
    float* out = (float*)d_out;

    const int SMEM_X    = 128 * LDXS * 2 * (int)sizeof(__nv_bfloat16);               // 69632
    const int SMEM_128  = SMEM_X + 4 * 128 * (128 + 8) * (int)sizeof(__nv_bfloat16); // 208896
    const int SMEM_64   = SMEM_X + 4 * 128 * (64 + 8)  * (int)sizeof(__nv_bfloat16); // 143360

    static __half *p_ylh = nullptr;
    static float *p_yr = nullptr, *p_A = nullptr, *p_B = nullptr;
    static int *p_cnt = nullptr, *p_off = nullptr, *p_cur = nullptr, *p_csr = nullptr, *p_bsum = nullptr;
    static cudaStream_t s_aux = nullptr;
    static cudaEvent_t ev[4];
    if (!p_yr) {
        cudaGetSymbolAddress((void**)&p_ylh,  g_ylh);
        cudaGetSymbolAddress((void**)&p_yr,   g_yr);
        cudaGetSymbolAddress((void**)&p_A,    g_bufA);
        cudaGetSymbolAddress((void**)&p_B,    g_bufB);
        cudaGetSymbolAddress((void**)&p_cnt,  g_cnt);
        cudaGetSymbolAddress((void**)&p_off,  g_off);
        cudaGetSymbolAddress((void**)&p_cur,  g_cur);
        cudaGetSymbolAddress((void**)&p_csr,  g_csr);
        cudaGetSymbolAddress((void**)&p_bsum, g_bsum);
        cudaStreamCreateWithFlags(&s_aux, cudaStreamNonBlocking);
        for (int i = 0; i < 4; i++)
            cudaEventCreateWithFlags(&ev[i], cudaEventDisableTiming);
        cudaFuncSetAttribute(gemm_dual_bf16<128, false>,
                             cudaFuncAttributeMaxDynamicSharedMemorySize, SMEM_128);
        cudaFuncSetAttribute(gemm_dual_bf16<128, true>,
                             cudaFuncAttributeMaxDynamicSharedMemorySize, SMEM_128);
        cudaFuncSetAttribute(gemm_dual_bf16<64, true>,
                             cudaFuncAttributeMaxDynamicSharedMemorySize, SMEM_64);
    }

    const int NB_SCAN  = (N_NODES + 1023) / 1024;
    const int NB_EDGE  = (N_EDGES + 255) / 256;
    const int NB_G128  = (N_NODES * 32 + 255) / 256;
    const int NB_G64   = (N_NODES * 16 + 255) / 256;

    // Fork aux stream: CSR build overlaps GEMM0.
    cudaEventRecord(ev[0], 0);
    cudaStreamWaitEvent(s_aux, ev[0], 0);
    detect_kernel<<<1, 1, 0, s_aux>>>(ei);
    zero_int_kernel<<<(N_NODES + 255) / 256, 256, 0, s_aux>>>(p_cnt, N_NODES);
    hist_kernel<<<NB_EDGE, 256, 0, s_aux>>>(ei, p_cnt);
    blockreduce_kernel<<<NB_SCAN, 256, 0, s_aux>>>(p_cnt, p_bsum);
    scanpart_kernel<<<1, 32, 0, s_aux>>>(p_bsum, NB_SCAN);
    scanfinal_kernel<<<NB_SCAN, 256, 0, s_aux>>>(p_cnt, p_bsum, p_off, p_cur);
    fill_kernel<<<NB_EDGE, 256, 0, s_aux>>>(ei, p_cur, p_csr);
    cudaEventRecord(ev[1], s_aux);

    // ---- Layer 0 ----
    gemm_dual_bf16<128, false><<<NSM, 512, SMEM_128>>>(
        x, nullptr, nullptr, nullptr, nullptr, Wl0, Wr0, p_ylh, p_yr);
    cudaStreamWaitEvent(0, ev[1], 0);   // CSR ready before gather
    gather128_h_kernel<<<NB_G128, 256>>>(p_ylh, p_csr, p_off, p_cnt, p_A);

    // ---- Layer 1 ----
    gemm_dual_bf16<128, true><<<NSM, 512, SMEM_128>>>(
        nullptr, p_A, p_yr, p_cnt, b0, Wl1, Wr1, p_ylh, p_yr);
    gather128_h_kernel<<<NB_G128, 256>>>(p_ylh, p_csr, p_off, p_cnt, p_B);

    // ---- Layer 2 (64 ch; gather fused with final combine -> d_out) ----
    gemm_dual_bf16<64, true><<<NSM, 512, SMEM_64>>>(
        nullptr, p_B, p_yr, p_cnt, b1, Wl2, Wr2, p_ylh, p_yr);
    gather64_fused_kernel<<<NB_G64, 256>>>(p_ylh, p_yr, b2, p_csr, p_off, p_cnt, out);
}

// round 15
// speedup vs baseline: 2.1349x; 1.2578x over previous
#include <cuda_runtime.h>
#include <cuda_fp16.h>
#include <mma.h>
#include <cstdint>

using namespace nvcuda;

// ---------------------------------------------------------------------------
// GraphSAGE 3-layer, aggregate-then-transform, all-fp16 activations:
//   h' = relu( (gather(h)/deg) @ Wl + h @ Wr + b )
// ONE fused GEMM per layer: acc = G@Wlh + G@Wll + H@Wrh + H@Wrl
// (A exact fp16, W split fp16 hi/lo -> no Markidis A-split, 4 mma/update).
// Persistent GEMM blocks, WM4 x WN4 x MFRAG2 tiling (R14 winner).
// ---------------------------------------------------------------------------

#define N_NODES 100000
#define N_EDGES 1600000
#define LDXS 136   // A smem leading dim (half elems); 272B rows
#define NSM 148

__device__ __half g_xh[(size_t)N_NODES * 128];
__device__ __half g_hA[(size_t)N_NODES * 128];
__device__ __half g_hB[(size_t)N_NODES * 128];
__device__ __half g_G [(size_t)N_NODES * 128];
__device__ int    g_cnt[N_NODES];
__device__ int    g_off[N_NODES];
__device__ int    g_cur[N_NODES];
__device__ int    g_csr[N_EDGES];
__device__ int    g_bsum[128];
__device__ int    g_is64;

// --------------------------- edge dtype probe ------------------------------
__global__ void detect_kernel(const void* ei) {
    const long long* e64 = (const long long*)ei;
    int is64 = 1;
    for (int i = 0; i < 64; i++) {
        long long v = e64[i];
        if (v < 0 || v >= N_NODES) { is64 = 0; break; }
    }
    g_is64 = is64;
}

__device__ __forceinline__ int load_idx(const void* ei, long long pos) {
    if (g_is64) return (int)((const long long*)ei)[pos];
    return ((const int*)ei)[pos];
}

// ------------------------------- CSR build ---------------------------------
__global__ void zero_int_kernel(int* __restrict__ p, int n) {
    int i = blockIdx.x * blockDim.x + threadIdx.x;
    if (i < n) p[i] = 0;
}

__global__ void hist_kernel(const void* __restrict__ ei, int* __restrict__ cnt) {
    int e = blockIdx.x * blockDim.x + threadIdx.x;
    if (e < N_EDGES) {
        int d = load_idx(ei, (long long)N_EDGES + e);
        if ((unsigned)d < N_NODES) atomicAdd(&cnt[d], 1);
    }
}

__global__ void blockreduce_kernel(const int* __restrict__ cnt, int* __restrict__ bsum) {
    __shared__ int sm[256];
    int b = blockIdx.x, t = threadIdx.x;
    int base = b * 1024 + t * 4;
    int s = 0;
    #pragma unroll
    for (int i = 0; i < 4; i++) {
        int idx = base + i;
        if (idx < N_NODES) s += cnt[idx];
    }
    sm[t] = s; __syncthreads();
    for (int st = 128; st > 0; st >>= 1) {
        if (t < st) sm[t] += sm[t + st];
        __syncthreads();
    }
    if (t == 0) bsum[b] = sm[0];
}

__global__ void scanpart_kernel(int* __restrict__ bsum, int nb) {
    if (threadIdx.x == 0) {
        int acc = 0;
        for (int i = 0; i < nb; i++) { int v = bsum[i]; bsum[i] = acc; acc += v; }
    }
}

__global__ void scanfinal_kernel(const int* __restrict__ cnt, const int* __restrict__ bsum,
                                 int* __restrict__ off, int* __restrict__ cur) {
    __shared__ int sm[256];
    int b = blockIdx.x, t = threadIdx.x;
    int base = b * 1024 + t * 4;
    int v[4]; int s = 0;
    #pragma unroll
    for (int i = 0; i < 4; i++) {
        int idx = base + i;
        v[i] = (idx < N_NODES) ? cnt[idx] : 0;
        s += v[i];
    }
    sm[t] = s; __syncthreads();
    for (int st = 1; st < 256; st <<= 1) {
        int x = (t >= st) ? sm[t - st] : 0;
        __syncthreads();
        sm[t] += x;
        __syncthreads();
    }
    int run = sm[t] - s + bsum[b];
    #pragma unroll
    for (int i = 0; i < 4; i++) {
        int idx = base + i;
        if (idx < N_NODES) { off[idx] = run; cur[idx] = run; }
        run += v[i];
    }
}

__global__ void fill_kernel(const void* __restrict__ ei, int* __restrict__ cur,
                            int* __restrict__ csr) {
    int e = blockIdx.x * blockDim.x + threadIdx.x;
    if (e < N_EDGES) {
        int s = load_idx(ei, e);
        int d = load_idx(ei, (long long)N_EDGES + e);
        if ((unsigned)s < N_NODES && (unsigned)d < N_NODES) {
            int p = atomicAdd(&cur[d], 1);
            csr[p] = s;
        }
    }
}

// ------------------------- x fp32 -> fp16 convert ---------------------------
__global__ void conv_f2h_kernel(const float* __restrict__ x, __half* __restrict__ xh, int n4) {
    int i = blockIdx.x * blockDim.x + threadIdx.x;
    if (i < n4) {
        float4 v = reinterpret_cast<const float4*>(x)[i];
        __half2 h0 = __floats2half2_rn(v.x, v.y);
        __half2 h1 = __floats2half2_rn(v.z, v.w);
        uint2 p;
        p.x = *reinterpret_cast<unsigned*>(&h0);
        p.y = *reinterpret_cast<unsigned*>(&h1);
        reinterpret_cast<uint2*>(xh)[i] = p;
    }
}

// ---------------------------------------------------------------------------
// Gather: G[n] = fp16( sum_{s in N(n)} h[s] )   (128 ch, one warp per node)
// ---------------------------------------------------------------------------
__device__ __forceinline__ void acc_h4(float4& acc, uint2 raw) {
    __half2 p0 = *reinterpret_cast<__half2*>(&raw.x);
    __half2 p1 = *reinterpret_cast<__half2*>(&raw.y);
    float2 f0 = __half22float2(p0);
    float2 f1 = __half22float2(p1);
    acc.x += f0.x; acc.y += f0.y; acc.z += f1.x; acc.w += f1.y;
}

__global__ __launch_bounds__(256) void gather128_h16_kernel(
    const __half* __restrict__ h,
    const int* __restrict__ csr, const int* __restrict__ off,
    const int* __restrict__ cnt, __half* __restrict__ G)
{
    int warp = (blockIdx.x * 256 + threadIdx.x) >> 5;
    int lane = threadIdx.x & 31;
    if (warp >= N_NODES) return;

    const int c = cnt[warp];
    const int o = off[warp];
    const uint2* __restrict__ h2 = reinterpret_cast<const uint2*>(h);

    float4 acc = make_float4(0.f, 0.f, 0.f, 0.f);
    int j = 0;
    for (; j + 4 <= c; j += 4) {
        int s0 = csr[o + j + 0];
        int s1 = csr[o + j + 1];
        int s2 = csr[o + j + 2];
        int s3 = csr[o + j + 3];
        uint2 a0 = h2[(size_t)s0 * 32 + lane];
        uint2 a1 = h2[(size_t)s1 * 32 + lane];
        uint2 a2 = h2[(size_t)s2 * 32 + lane];
        uint2 a3 = h2[(size_t)s3 * 32 + lane];
        acc_h4(acc, a0); acc_h4(acc, a1); acc_h4(acc, a2); acc_h4(acc, a3);
    }
    for (; j < c; j++) {
        int s = csr[o + j];
        acc_h4(acc, h2[(size_t)s * 32 + lane]);
    }
    __half2 o0 = __floats2half2_rn(acc.x, acc.y);
    __half2 o1 = __floats2half2_rn(acc.z, acc.w);
    uint2 p;
    p.x = *reinterpret_cast<unsigned*>(&o0);
    p.y = *reinterpret_cast<unsigned*>(&o1);
    reinterpret_cast<uint2*>(G)[(size_t)warp * 32 + lane] = p;
}

// ---------------------------------------------------------------------------
// Fused layer GEMM (persistent, 512 thr, grid=NSM):
//   acc = (G/deg)@Wlh + (G/deg)@Wll + H@Wrh + H@Wrl
//   out = RELU ? fp16(relu(acc+b)) : fp32(acc+b)
// A inputs fp16 exact; W split fp16 hi/lo in-kernel (once per block).
// Tiling: 16 warps = WM4 x WN4; warp = 32 rows (MFRAG=2) x DOUT/4 cols.
// ---------------------------------------------------------------------------
template <int DOUT, bool RELU, bool F16OUT>
__global__ __launch_bounds__(512) void gemm_fused(
    const __half* __restrict__ G, const __half* __restrict__ H,
    const int* __restrict__ cnt,
    const float* __restrict__ Wl, const float* __restrict__ Wr,
    const float* __restrict__ bias,
    __half* __restrict__ Yh, float* __restrict__ Yf)
{
    constexpr int LDW = DOUT + 8;
    constexpr int NT = (N_NODES + 127) / 128;   // 782 tiles
    extern __shared__ __half smem[];
    __half* sG   = smem;                    // [128][LDXS]
    __half* sH   = sG + 128 * LDXS;         // [128][LDXS]
    __half* sWlh = sH + 128 * LDXS;         // [128][LDW]
    __half* sWll = sWlh + 128 * LDW;
    __half* sWrh = sWll + 128 * LDW;
    __half* sWrl = sWrh + 128 * LDW;

    const int t = threadIdx.x;

    // ---- stage + split W ONCE (fp32 -> fp16 hi/lo; w-error ~2^-22) ----
    {
        constexpr int C4 = DOUT / 4;
        const float4* gl = reinterpret_cast<const float4*>(Wl);
        const float4* gr = reinterpret_cast<const float4*>(Wr);
        for (int i = t; i < 128 * C4; i += 512) {
            int k = i / C4, c4 = i % C4;
            int so = k * LDW + c4 * 4;
            float4 wl = gl[i];
            float4 wr = gr[i];
            __half hx, hy, hz, hw;
            hx = __float2half_rn(wl.x); hy = __float2half_rn(wl.y);
            hz = __float2half_rn(wl.z); hw = __float2half_rn(wl.w);
            sWlh[so] = hx; sWlh[so+1] = hy; sWlh[so+2] = hz; sWlh[so+3] = hw;
            sWll[so]   = __float2half_rn(wl.x - __half2float(hx));
            sWll[so+1] = __float2half_rn(wl.y - __half2float(hy));
            sWll[so+2] = __float2half_rn(wl.z - __half2float(hz));
            sWll[so+3] = __float2half_rn(wl.w - __half2float(hw));
            hx = __float2half_rn(wr.x); hy = __float2half_rn(wr.y);
            hz = __float2half_rn(wr.z); hw = __float2half_rn(wr.w);
            sWrh[so] = hx; sWrh[so+1] = hy; sWrh[so+2] = hz; sWrh[so+3] = hw;
            sWrl[so]   = __float2half_rn(wr.x - __half2float(hx));
            sWrl[so+1] = __float2half_rn(wr.y - __half2float(hy));
            sWrl[so+2] = __float2half_rn(wr.z - __half2float(hz));
            sWrl[so+3] = __float2half_rn(wr.w - __half2float(hw));
        }
    }

    // warp tiling: WM4 x WN4, MFRAG=2
    constexpr int NF = DOUT / 64;          // 2 or 1
    const int warp = t >> 5;
    const int wm = warp & 3;
    const int wn = warp >> 2;
    const int mbase = wm * 32;
    const int nbase = wn * (DOUT / 4);

    const uint2* __restrict__ G2 = reinterpret_cast<const uint2*>(G);
    const uint2* __restrict__ H2 = reinterpret_cast<const uint2*>(H);

    for (int tile = blockIdx.x; tile < NT; tile += gridDim.x) {
        const int row0 = tile * 128;

        // ---- prologue: copy H, load G and scale by 1/deg ----
        for (int i = t; i < 128 * 32; i += 512) {
            int r = i >> 5, c = i & 31;
            int gr = row0 + r;
            uint2 gv = make_uint2(0u, 0u);
            uint2 hv = make_uint2(0u, 0u);
            if (gr < N_NODES) {
                gv = G2[(size_t)gr * 32 + c];
                hv = H2[(size_t)gr * 32 + c];
                float dinv = 1.0f / fmaxf((float)cnt[gr], 1.0f);
                __half2 p0 = *reinterpret_cast<__half2*>(&gv.x);
                __half2 p1 = *reinterpret_cast<__half2*>(&gv.y);
                float2 f0 = __half22float2(p0);
                float2 f1 = __half22float2(p1);
                __half2 q0 = __floats2half2_rn(f0.x * dinv, f0.y * dinv);
                __half2 q1 = __floats2half2_rn(f1.x * dinv, f1.y * dinv);
                gv.x = *reinterpret_cast<unsigned*>(&q0);
                gv.y = *reinterpret_cast<unsigned*>(&q1);
            }
            int base = r * LDXS + c * 4;
            *reinterpret_cast<uint2*>(&sG[base]) = gv;
            *reinterpret_cast<uint2*>(&sH[base]) = hv;
        }
        __syncthreads();

        wmma::fragment<wmma::accumulator, 16, 16, 16, float> acc[2][NF];
        #pragma unroll
        for (int mf = 0; mf < 2; mf++)
            #pragma unroll
            for (int nf = 0; nf < NF; nf++)
                wmma::fill_fragment(acc[mf][nf], 0.0f);

        #pragma unroll
        for (int k = 0; k < 128; k += 16) {
            wmma::fragment<wmma::matrix_a, 16, 16, 16, __half, wmma::row_major> ga[2], ha[2];
            #pragma unroll
            for (int mf = 0; mf < 2; mf++) {
                wmma::load_matrix_sync(ga[mf], &sG[(mbase + mf * 16) * LDXS + k], LDXS);
                wmma::load_matrix_sync(ha[mf], &sH[(mbase + mf * 16) * LDXS + k], LDXS);
            }
            #pragma unroll
            for (int nf = 0; nf < NF; nf++) {
                int n0 = nbase + nf * 16;
                wmma::fragment<wmma::matrix_b, 16, 16, 16, __half, wmma::row_major> blh, bll, brh, brl;
                wmma::load_matrix_sync(blh, &sWlh[k * LDW + n0], LDW);
                wmma::load_matrix_sync(bll, &sWll[k * LDW + n0], LDW);
                wmma::load_matrix_sync(brh, &sWrh[k * LDW + n0], LDW);
                wmma::load_matrix_sync(brl, &sWrl[k * LDW + n0], LDW);
                #pragma unroll
                for (int mf = 0; mf < 2; mf++) {
                    wmma::mma_sync(acc[mf][nf], ga[mf], blh, acc[mf][nf]);
                    wmma::mma_sync(acc[mf][nf], ga[mf], bll, acc[mf][nf]);
                    wmma::mma_sync(acc[mf][nf], ha[mf], brh, acc[mf][nf]);
                    wmma::mma_sync(acc[mf][nf], ha[mf], brl, acc[mf][nf]);
                }
            }
        }

        // ---- epilogue: restage acc in smem (reuse A region), +b, relu, store ----
        constexpr int LDE = DOUT + 4;
        float* sEp = reinterpret_cast<float*>(smem);   // [128][LDE] fp32 in A region
        __syncthreads();
        #pragma unroll
        for (int mf = 0; mf < 2; mf++)
            #pragma unroll
            for (int nf = 0; nf < NF; nf++)
                wmma::store_matrix_sync(&sEp[(mbase + mf * 16) * LDE + nbase + nf * 16],
                                        acc[mf][nf], LDE, wmma::mem_row_major);
        __syncthreads();
        {
            constexpr int C4 = DOUT / 4;
            for (int i = t; i < 128 * C4; i += 512) {
                int r = i / C4, c4 = i % C4;
                int gr = row0 + r;
                if (gr < N_NODES) {
                    float4 v = *reinterpret_cast<const float4*>(&sEp[r * LDE + c4 * 4]);
                    float4 bb = reinterpret_cast<const float4*>(bias)[c4];
                    v.x += bb.x; v.y += bb.y; v.z += bb.z; v.w += bb.w;
                    if (RELU) {
                        v.x = fmaxf(v.x, 0.f); v.y = fmaxf(v.y, 0.f);
                        v.z = fmaxf(v.z, 0.f); v.w = fmaxf(v.w, 0.f);
                    }
                    if (F16OUT) {
                        __half2 h0 = __floats2half2_rn(v.x, v.y);
                        __half2 h1 = __floats2half2_rn(v.z, v.w);
                        uint2 p;
                        p.x = *reinterpret_cast<unsigned*>(&h0);
                        p.y = *reinterpret_cast<unsigned*>(&h1);
                        *reinterpret_cast<uint2*>(Yh + (size_t)gr * DOUT + c4 * 4) = p;
                    } else {
                        *reinterpret_cast<float4*>(Yf + (size_t)gr * DOUT + c4 * 4) = v;
                    }
                }
            }
        }
        __syncthreads();   // sEp (A region) fully consumed before next tile
    }
}

// ---------------------------------------------------------------------------
extern "C" void kernel_launch(void* const* d_in, const int* in_sizes, int n_in,
                              void* d_out, int out_size)
{
    const float* x   = (const float*)d_in[0];
    const void*  ei  = d_in[1];
    const float* Wl0 = (const float*)d_in[2];
    const float* Wr0 = (const float*)d_in[3];
    const float* b0  = (const float*)d_in[4];
    const float* Wl1 = (const float*)d_in[5];
    const float* Wr1 = (const float*)d_in[6];
    const float* b1  = (const float*)d_in[7];
    const float* Wl2 = (const float*)d_in[8];
    const float* Wr2 = (const float*)d_in[9];
    const float* b2  = (const float*)d_in[10];
    float* out = (float*)d_out;

    const int SMEM_A    = 2 * 128 * LDXS * (int)sizeof(__half);                // 69632
    const int SMEM_128  = SMEM_A + 4 * 128 * (128 + 8) * (int)sizeof(__half);  // 208896
    const int SMEM_64   = SMEM_A + 4 * 128 * (64 + 8)  * (int)sizeof(__half);  // 143360

    static __half *p_xh = nullptr, *p_hA = nullptr, *p_hB = nullptr, *p_G = nullptr;
    static int *p_cnt = nullptr, *p_off = nullptr, *p_cur = nullptr, *p_csr = nullptr, *p_bsum = nullptr;
    static cudaStream_t s_aux = nullptr;
    static cudaEvent_t ev[4];
    if (!p_xh) {
        cudaGetSymbolAddress((void**)&p_xh,   g_xh);
        cudaGetSymbolAddress((void**)&p_hA,   g_hA);
        cudaGetSymbolAddress((void**)&p_hB,   g_hB);
        cudaGetSymbolAddress((void**)&p_G,    g_G);
        cudaGetSymbolAddress((void**)&p_cnt,  g_cnt);
        cudaGetSymbolAddress((void**)&p_off,  g_off);
        cudaGetSymbolAddress((void**)&p_cur,  g_cur);
        cudaGetSymbolAddress((void**)&p_csr,  g_csr);
        cudaGetSymbolAddress((void**)&p_bsum, g_bsum);
        cudaStreamCreateWithFlags(&s_aux, cudaStreamNonBlocking);
        for (int i = 0; i < 4; i++)
            cudaEventCreateWithFlags(&ev[i], cudaEventDisableTiming);
        cudaFuncSetAttribute(gemm_fused<128, true, true>,
                             cudaFuncAttributeMaxDynamicSharedMemorySize, SMEM_128);
        cudaFuncSetAttribute(gemm_fused<64, false, false>,
                             cudaFuncAttributeMaxDynamicSharedMemorySize, SMEM_64);
    }

    const int NB_SCAN  = (N_NODES + 1023) / 1024;
    const int NB_EDGE  = (N_EDGES + 255) / 256;
    const int NB_G128  = (N_NODES * 32 + 255) / 256;
    const int NB_CONV  = (N_NODES * 32 + 255) / 256;

    // Fork aux stream: CSR build overlaps x->fp16 conversion.
    cudaEventRecord(ev[0], 0);
    cudaStreamWaitEvent(s_aux, ev[0], 0);
    detect_kernel<<<1, 1, 0, s_aux>>>(ei);
    zero_int_kernel<<<(N_NODES + 255) / 256, 256, 0, s_aux>>>(p_cnt, N_NODES);
    hist_kernel<<<NB_EDGE, 256, 0, s_aux>>>(ei, p_cnt);
    blockreduce_kernel<<<NB_SCAN, 256, 0, s_aux>>>(p_cnt, p_bsum);
    scanpart_kernel<<<1, 32, 0, s_aux>>>(p_bsum, NB_SCAN);
    scanfinal_kernel<<<NB_SCAN, 256, 0, s_aux>>>(p_cnt, p_bsum, p_off, p_cur);
    fill_kernel<<<NB_EDGE, 256, 0, s_aux>>>(ei, p_cur, p_csr);
    cudaEventRecord(ev[1], s_aux);

    // x -> fp16 (main)
    conv_f2h_kernel<<<NB_CONV, 256>>>(x, p_xh, N_NODES * 32);

    // ---- Layer 0: gather(xh) -> G;  h1 = relu(G/deg@Wl0 + xh@Wr0 + b0) ----
    cudaStreamWaitEvent(0, ev[1], 0);
    gather128_h16_kernel<<<NB_G128, 256>>>(p_xh, p_csr, p_off, p_cnt, p_G);
    gemm_fused<128, true, true><<<NSM, 512, SMEM_128>>>(
        p_G, p_xh, p_cnt, Wl0, Wr0, b0, p_hA, nullptr);

    // ---- Layer 1 ----
    gather128_h16_kernel<<<NB_G128, 256>>>(p_hA, p_csr, p_off, p_cnt, p_G);
    gemm_fused<128, true, true><<<NSM, 512, SMEM_128>>>(
        p_G, p_hA, p_cnt, Wl1, Wr1, b1, p_hB, nullptr);

    // ---- Layer 2 (64 out, no relu, fp32 -> d_out) ----
    gather128_h16_kernel<<<NB_G128, 256>>>(p_hB, p_csr, p_off, p_cnt, p_G);
    gemm_fused<64, false, false><<<NSM, 512, SMEM_64>>>(
        p_G, p_hB, p_cnt, Wl2, Wr2, b2, nullptr, out);
}